// round 1
// baseline (speedup 1.0000x reference)
#include <cuda_runtime.h>

#define DIMC 1024
#define NB   4
#define NSEQ 2048
#define NH   16
#define DH   64
#define MT   (NB * NSEQ)      // 8192 rows
#define QKVN (3 * DIMC)       // 3072
#define SCALE 0.125f          // 64^-0.5

// Scratch (static device globals: allocation-free per harness rules)
__device__ float g_qkv[(size_t)MT * QKVN];   // [8192][3072]  q|k|v interleaved per row
__device__ float g_attn[(size_t)MT * DIMC];  // [8192][1024]  attention output

// ---------------------------------------------------------------------------
// SGEMM NT: C[M,N] = A[M,K] * B[N,K]^T   (A, B row-major, K contiguous)
// 128x128 block tile, BK=16, 8x8 per thread, 256 threads.
// ---------------------------------------------------------------------------
__global__ void __launch_bounds__(256)
sgemm_nt(const float* __restrict__ A, const float* __restrict__ B,
         float* __restrict__ C, int M, int N, int K)
{
    __shared__ float As[16][128 + 4];
    __shared__ float Bs[16][128 + 4];

    const int tid = threadIdx.x;
    const int bm  = blockIdx.y * 128;
    const int bn  = blockIdx.x * 128;
    const int ty  = tid >> 4;          // 0..15
    const int tx  = tid & 15;          // 0..15
    const int lrow = tid >> 2;         // 0..63
    const int lcol = (tid & 3) << 2;   // 0,4,8,12

    const float* Ap = A + (size_t)(bm + lrow) * K + lcol;
    const float* Bp = B + (size_t)(bn + lrow) * K + lcol;

    float acc[8][8];
#pragma unroll
    for (int i = 0; i < 8; i++)
#pragma unroll
        for (int j = 0; j < 8; j++) acc[i][j] = 0.f;

    for (int k0 = 0; k0 < K; k0 += 16) {
        float4 a0 = *(const float4*)(Ap + k0);
        float4 a1 = *(const float4*)(Ap + (size_t)64 * K + k0);
        float4 b0 = *(const float4*)(Bp + k0);
        float4 b1 = *(const float4*)(Bp + (size_t)64 * K + k0);
        __syncthreads();
        As[lcol + 0][lrow]      = a0.x; As[lcol + 1][lrow]      = a0.y;
        As[lcol + 2][lrow]      = a0.z; As[lcol + 3][lrow]      = a0.w;
        As[lcol + 0][lrow + 64] = a1.x; As[lcol + 1][lrow + 64] = a1.y;
        As[lcol + 2][lrow + 64] = a1.z; As[lcol + 3][lrow + 64] = a1.w;
        Bs[lcol + 0][lrow]      = b0.x; Bs[lcol + 1][lrow]      = b0.y;
        Bs[lcol + 2][lrow]      = b0.z; Bs[lcol + 3][lrow]      = b0.w;
        Bs[lcol + 0][lrow + 64] = b1.x; Bs[lcol + 1][lrow + 64] = b1.y;
        Bs[lcol + 2][lrow + 64] = b1.z; Bs[lcol + 3][lrow + 64] = b1.w;
        __syncthreads();

#pragma unroll
        for (int kk = 0; kk < 16; kk++) {
            float ar[8], br[8];
            float4 t0 = *(const float4*)&As[kk][ty * 8];
            float4 t1 = *(const float4*)&As[kk][ty * 8 + 4];
            ar[0] = t0.x; ar[1] = t0.y; ar[2] = t0.z; ar[3] = t0.w;
            ar[4] = t1.x; ar[5] = t1.y; ar[6] = t1.z; ar[7] = t1.w;
            float4 u0 = *(const float4*)&Bs[kk][tx * 8];
            float4 u1 = *(const float4*)&Bs[kk][tx * 8 + 4];
            br[0] = u0.x; br[1] = u0.y; br[2] = u0.z; br[3] = u0.w;
            br[4] = u1.x; br[5] = u1.y; br[6] = u1.z; br[7] = u1.w;
#pragma unroll
            for (int i = 0; i < 8; i++)
#pragma unroll
                for (int j = 0; j < 8; j++)
                    acc[i][j] += ar[i] * br[j];
        }
    }

#pragma unroll
    for (int i = 0; i < 8; i++) {
        float* crow = C + (size_t)(bm + ty * 8 + i) * N + bn + tx * 8;
        *(float4*)(crow)     = make_float4(acc[i][0], acc[i][1], acc[i][2], acc[i][3]);
        *(float4*)(crow + 4) = make_float4(acc[i][4], acc[i][5], acc[i][6], acc[i][7]);
    }
}

// ---------------------------------------------------------------------------
// Flash attention, fp32. One block = one (b,h) x 64-query tile.
// KV tiles of 32. 256 threads: 16x16 layout.
//   S phase : thread (ty,tx) owns rows 4ty..4ty+3, cols 2tx..2tx+1 of S[64x32]
//   PV phase: thread (ty,tx) owns rows 4ty..4ty+3, dcols 4tx..4tx+3 of O[64x64]
// Row softmax stats reduced over the 16 tx lanes via shfl.xor (1,2,4,8).
// ---------------------------------------------------------------------------
__global__ void __launch_bounds__(256)
flash_attn(const float* __restrict__ qkv, float* __restrict__ out)
{
    __shared__ float Qs[64][DH + 1];   // pad -> conflict-free row reads
    __shared__ float Ks[32][DH + 1];
    __shared__ float Vs[32][DH];
    __shared__ float Ps[64][33];

    const int tid = threadIdx.x;
    const int b   = blockIdx.y >> 4;
    const int h   = blockIdx.y & 15;
    const int n0  = blockIdx.x * 64;
    const int ty  = tid >> 4;
    const int tx  = tid & 15;

    const size_t base = ((size_t)b * NSEQ) * QKVN + (size_t)h * DH;

    // Load Q tile (64 x 64)
#pragma unroll
    for (int p = 0; p < 4; p++) {
        int f = tid + p * 256;
        int r = f >> 4;
        int c = (f & 15) << 2;
        float4 v = *(const float4*)(qkv + base + (size_t)(n0 + r) * QKVN + c);
        Qs[r][c] = v.x; Qs[r][c + 1] = v.y; Qs[r][c + 2] = v.z; Qs[r][c + 3] = v.w;
    }

    const float NEG_INF = __int_as_float(0xff800000);
    float m_run[4], l_run[4], o[4][4];
#pragma unroll
    for (int i = 0; i < 4; i++) {
        m_run[i] = NEG_INF;
        l_run[i] = 0.f;
#pragma unroll
        for (int j = 0; j < 4; j++) o[i][j] = 0.f;
    }

    for (int kv0 = 0; kv0 < NSEQ; kv0 += 32) {
        __syncthreads();   // prior PV reads done; Q ready on first iter
        // Load K,V tiles (32 x 64 each)
#pragma unroll
        for (int p = 0; p < 2; p++) {
            int f = tid + p * 256;
            int r = f >> 4;
            int c = (f & 15) << 2;
            const float* rowp = qkv + base + (size_t)(kv0 + r) * QKVN;
            float4 kv4 = *(const float4*)(rowp + DIMC + c);
            Ks[r][c] = kv4.x; Ks[r][c + 1] = kv4.y; Ks[r][c + 2] = kv4.z; Ks[r][c + 3] = kv4.w;
            float4 vv  = *(const float4*)(rowp + 2 * DIMC + c);
            *(float4*)&Vs[r][c] = vv;
        }
        __syncthreads();

        // S = SCALE * Q K^T
        float s[4][2] = {{0.f, 0.f}, {0.f, 0.f}, {0.f, 0.f}, {0.f, 0.f}};
#pragma unroll 16
        for (int d = 0; d < DH; d++) {
            float b0 = Ks[2 * tx][d];
            float b1 = Ks[2 * tx + 1][d];
#pragma unroll
            for (int i = 0; i < 4; i++) {
                float a = Qs[4 * ty + i][d];
                s[i][0] += a * b0;
                s[i][1] += a * b1;
            }
        }

        float mt[4], pj[4][2], rs[4], corr[4];
#pragma unroll
        for (int i = 0; i < 4; i++) {
            s[i][0] *= SCALE; s[i][1] *= SCALE;
            mt[i] = fmaxf(s[i][0], s[i][1]);
            mt[i] = fmaxf(mt[i], __shfl_xor_sync(0xffffffffu, mt[i], 1));
            mt[i] = fmaxf(mt[i], __shfl_xor_sync(0xffffffffu, mt[i], 2));
            mt[i] = fmaxf(mt[i], __shfl_xor_sync(0xffffffffu, mt[i], 4));
            mt[i] = fmaxf(mt[i], __shfl_xor_sync(0xffffffffu, mt[i], 8));
        }
#pragma unroll
        for (int i = 0; i < 4; i++) {
            float m_new = fmaxf(m_run[i], mt[i]);
            corr[i] = __expf(m_run[i] - m_new);
            pj[i][0] = __expf(s[i][0] - m_new);
            pj[i][1] = __expf(s[i][1] - m_new);
            rs[i] = pj[i][0] + pj[i][1];
            m_run[i] = m_new;
            rs[i] += __shfl_xor_sync(0xffffffffu, rs[i], 1);
            rs[i] += __shfl_xor_sync(0xffffffffu, rs[i], 2);
            rs[i] += __shfl_xor_sync(0xffffffffu, rs[i], 4);
            rs[i] += __shfl_xor_sync(0xffffffffu, rs[i], 8);
            l_run[i] = l_run[i] * corr[i] + rs[i];
        }

        // Stage P to smem for the PV GEMM
#pragma unroll
        for (int i = 0; i < 4; i++) {
            Ps[4 * ty + i][2 * tx]     = pj[i][0];
            Ps[4 * ty + i][2 * tx + 1] = pj[i][1];
        }
        __syncthreads();

        // O = diag(corr) O + P V
#pragma unroll
        for (int i = 0; i < 4; i++)
#pragma unroll
            for (int j = 0; j < 4; j++) o[i][j] *= corr[i];

#pragma unroll 8
        for (int c = 0; c < 32; c++) {
            float vr[4];
#pragma unroll
            for (int j = 0; j < 4; j++) vr[j] = Vs[c][4 * tx + j];
#pragma unroll
            for (int i = 0; i < 4; i++) {
                float pr = Ps[4 * ty + i][c];
#pragma unroll
                for (int j = 0; j < 4; j++) o[i][j] += pr * vr[j];
            }
        }
    }

    // Epilogue: normalize and write [b, n, h, d]
#pragma unroll
    for (int i = 0; i < 4; i++) {
        float inv = 1.f / l_run[i];
        size_t off = ((size_t)b * NSEQ + n0 + 4 * ty + i) * DIMC + h * DH + 4 * tx;
        *(float4*)&out[off] = make_float4(o[i][0] * inv, o[i][1] * inv,
                                          o[i][2] * inv, o[i][3] * inv);
    }
}

// ---------------------------------------------------------------------------
extern "C" void kernel_launch(void* const* d_in, const int* in_sizes, int n_in,
                              void* d_out, int out_size)
{
    (void)in_sizes; (void)n_in; (void)out_size;
    const float* x      = (const float*)d_in[0];
    const float* w_qkv  = (const float*)d_in[1];
    const float* w_proj = (const float*)d_in[2];
    float* out = (float*)d_out;

    float *qkv_p, *attn_p;
    cudaGetSymbolAddress((void**)&qkv_p,  g_qkv);   // query only — capture-safe
    cudaGetSymbolAddress((void**)&attn_p, g_attn);

    // 1) QKV projection: [8192,3072] = x[8192,1024] @ w_qkv[3072,1024]^T
    dim3 g1(QKVN / 128, MT / 128);
    sgemm_nt<<<g1, 256>>>(x, w_qkv, qkv_p, MT, QKVN, DIMC);

    // 2) Attention
    dim3 g2(NSEQ / 64, NB * NH);
    flash_attn<<<g2, 256>>>(qkv_p, attn_p);

    // 3) Output projection: [8192,1024] = attn @ w_proj[1024,1024]^T
    dim3 g3(DIMC / 128, MT / 128);
    sgemm_nt<<<g3, 256>>>(attn_p, w_proj, out, MT, DIMC, DIMC);
}

// round 3
// speedup vs baseline: 1.2498x; 1.2498x over previous
#include <cuda_runtime.h>
#include <cuda_bf16.h>
#include <cstdint>

#define DIMC 1024
#define NB   4
#define NSEQ 2048
#define NH   16
#define DH   64
#define MT   (NB * NSEQ)      // 8192 rows
#define QKVN (3 * DIMC)       // 3072
#define SCALE 0.125f          // 64^-0.5

// ---------------- scratch (static device globals: allocation-free) ----------
__device__ float g_qkv[(size_t)MT * QKVN];            // [8192][3072] fp32 q|k|v
__device__ __nv_bfloat16 g_xh[(size_t)MT * DIMC];
__device__ __nv_bfloat16 g_xl[(size_t)MT * DIMC];
__device__ __nv_bfloat16 g_wqh[(size_t)QKVN * DIMC];
__device__ __nv_bfloat16 g_wql[(size_t)QKVN * DIMC];
__device__ __nv_bfloat16 g_wph[(size_t)DIMC * DIMC];
__device__ __nv_bfloat16 g_wpl[(size_t)DIMC * DIMC];
__device__ __nv_bfloat16 g_ah[(size_t)MT * DIMC];
__device__ __nv_bfloat16 g_al[(size_t)MT * DIMC];

// ---------------- PTX helpers (baseline ISA only: mma.sync + cp.async) ------
__device__ __forceinline__ uint32_t smem_u32_of(const void* p) {
    uint32_t a;
    asm("{ .reg .u64 t; cvta.to.shared.u64 t, %1; cvt.u32.u64 %0, t; }"
        : "=r"(a) : "l"(p));
    return a;
}
__device__ __forceinline__ void cp16(uint32_t dst, const void* src) {
    asm volatile("cp.async.cg.shared.global [%0], [%1], 16;" :: "r"(dst), "l"(src));
}
#define CP_COMMIT() asm volatile("cp.async.commit_group;" ::: "memory")
#define CP_WAIT(n)  asm volatile("cp.async.wait_group %0;" :: "n"(n) : "memory")

__device__ __forceinline__ uint32_t lds32(uint32_t a) {
    uint32_t v;
    asm volatile("ld.shared.b32 %0, [%1];" : "=r"(v) : "r"(a));
    return v;
}
__device__ __forceinline__ void mma16816(float* d, const uint32_t* a, const uint32_t* b) {
    asm volatile(
        "mma.sync.aligned.m16n8k16.row.col.f32.bf16.bf16.f32 "
        "{%0,%1,%2,%3}, {%4,%5,%6,%7}, {%8,%9}, {%0,%1,%2,%3};"
        : "+f"(d[0]), "+f"(d[1]), "+f"(d[2]), "+f"(d[3])
        : "r"(a[0]), "r"(a[1]), "r"(a[2]), "r"(a[3]), "r"(b[0]), "r"(b[1]));
}

// ---------------------------------------------------------------------------
// split fp32 -> bf16 hi/lo
// ---------------------------------------------------------------------------
__global__ void __launch_bounds__(256)
split_bf16(const float4* __restrict__ src, __nv_bfloat16* __restrict__ hi,
           __nv_bfloat16* __restrict__ lo, int n4)
{
    int i = blockIdx.x * blockDim.x + threadIdx.x;
    if (i >= n4) return;
    float4 v = src[i];
    __nv_bfloat16 h0 = __float2bfloat16(v.x), h1 = __float2bfloat16(v.y);
    __nv_bfloat16 h2 = __float2bfloat16(v.z), h3 = __float2bfloat16(v.w);
    __nv_bfloat16 l0 = __float2bfloat16(v.x - __bfloat162float(h0));
    __nv_bfloat16 l1 = __float2bfloat16(v.y - __bfloat162float(h1));
    __nv_bfloat16 l2 = __float2bfloat16(v.z - __bfloat162float(h2));
    __nv_bfloat16 l3 = __float2bfloat16(v.w - __bfloat162float(h3));
    size_t o = (size_t)i * 4;
    *(__nv_bfloat162*)(hi + o)     = __halves2bfloat162(h0, h1);
    *(__nv_bfloat162*)(hi + o + 2) = __halves2bfloat162(h2, h3);
    *(__nv_bfloat162*)(lo + o)     = __halves2bfloat162(l0, l1);
    *(__nv_bfloat162*)(lo + o + 2) = __halves2bfloat162(l2, l3);
}

// ---------------------------------------------------------------------------
// Split-bf16 HMMA GEMM NT: C[M,N] = (Ah+Al)[M,K] * (Bh+Bl)[N,K]^T  (fp32 C)
// 128x128 CTA tile, BK=32, 8 warps (2x4), warp tile 64x32 of m16n8k16.
// 3 MMAs per tile: hi*hi + hi*lo + lo*hi. 2-stage cp.async pipeline.
// SMEM row stride 80B (32 bf16 + 8 pad) -> conflict-free u32 fragment loads.
// ---------------------------------------------------------------------------
#define STRIDE_B 80                       // bytes per smem row
#define ARR_SZ   (128 * STRIDE_B)         // 10240 bytes per array
#define STAGE_SZ (4 * ARR_SZ)             // Ah, Al, Bh, Bl

__global__ void __launch_bounds__(256, 1)
gemm_hmma(const __nv_bfloat16* __restrict__ Ah, const __nv_bfloat16* __restrict__ Al,
          const __nv_bfloat16* __restrict__ Bh, const __nv_bfloat16* __restrict__ Bl,
          float* __restrict__ C, int M, int N, int K)
{
    extern __shared__ __align__(16) char dsm[];
    const uint32_t sb = smem_u32_of(dsm);

    const int tid  = threadIdx.x;
    const int wid  = tid >> 5;
    const int lane = tid & 31;
    const int wm   = wid & 1;             // 0..1  (64-row slabs)
    const int wn   = wid >> 1;            // 0..3  (32-col slabs)
    const int bm   = blockIdx.y * 128;
    const int bn   = blockIdx.x * 128;
    const int lr   = lane >> 2;           // 0..7
    const int lc2  = (lane & 3) * 2;      // 0,2,4,6 (k element pair)

    // load mapping: 512 16B-chunks per array per stage; 2 per thread
    const int r0 = (tid * 2) >> 2, c0 = (tid * 2) & 3;
    const int r1 = (tid * 2 + 1) >> 2, c1 = (tid * 2 + 1) & 3;

    float acc[4][4][4];
#pragma unroll
    for (int i = 0; i < 4; i++)
#pragma unroll
        for (int j = 0; j < 4; j++)
#pragma unroll
            for (int k = 0; k < 4; k++) acc[i][j][k] = 0.f;

    const int nk = K >> 5;                // K/32 chunks

    auto issue = [&](int chunk, int stage) {
        const int k0 = chunk << 5;
        const uint32_t s = sb + stage * STAGE_SZ;
        const size_t ga0 = (size_t)(bm + r0) * K + k0 + c0 * 8;
        const size_t ga1 = (size_t)(bm + r1) * K + k0 + c1 * 8;
        const size_t gb0 = (size_t)(bn + r0) * K + k0 + c0 * 8;
        const size_t gb1 = (size_t)(bn + r1) * K + k0 + c1 * 8;
        const uint32_t so0 = (uint32_t)(r0 * STRIDE_B + c0 * 16);
        const uint32_t so1 = (uint32_t)(r1 * STRIDE_B + c1 * 16);
        cp16(s + so0,              Ah + ga0);
        cp16(s + so1,              Ah + ga1);
        cp16(s + ARR_SZ + so0,     Al + ga0);
        cp16(s + ARR_SZ + so1,     Al + ga1);
        cp16(s + 2 * ARR_SZ + so0, Bh + gb0);
        cp16(s + 2 * ARR_SZ + so1, Bh + gb1);
        cp16(s + 3 * ARR_SZ + so0, Bl + gb0);
        cp16(s + 3 * ARR_SZ + so1, Bl + gb1);
    };

    issue(0, 0);
    CP_COMMIT();

    int stage = 0;
    for (int ch = 0; ch < nk; ch++) {
        if (ch + 1 < nk) {
            issue(ch + 1, stage ^ 1);
            CP_COMMIT();
            CP_WAIT(1);
        } else {
            CP_WAIT(0);
        }
        __syncthreads();

        const uint32_t sAh = sb + stage * STAGE_SZ;
        const uint32_t sAl = sAh + ARR_SZ;
        const uint32_t sBh = sAh + 2 * ARR_SZ;
        const uint32_t sBl = sAh + 3 * ARR_SZ;

#pragma unroll
        for (int ks = 0; ks < 2; ks++) {           // two k16 steps in BK=32
            const uint32_t kb = (uint32_t)((ks * 16 + lc2) * 2);  // byte offset in row
            uint32_t ah[4][4], al[4][4], bh[4][2], bl[4][2];
#pragma unroll
            for (int mt = 0; mt < 4; mt++) {
                uint32_t ro = (uint32_t)((wm * 64 + mt * 16 + lr) * STRIDE_B) + kb;
                ah[mt][0] = lds32(sAh + ro);
                ah[mt][1] = lds32(sAh + ro + 8 * STRIDE_B);
                ah[mt][2] = lds32(sAh + ro + 16);
                ah[mt][3] = lds32(sAh + ro + 8 * STRIDE_B + 16);
                al[mt][0] = lds32(sAl + ro);
                al[mt][1] = lds32(sAl + ro + 8 * STRIDE_B);
                al[mt][2] = lds32(sAl + ro + 16);
                al[mt][3] = lds32(sAl + ro + 8 * STRIDE_B + 16);
            }
#pragma unroll
            for (int nt = 0; nt < 4; nt++) {
                uint32_t ro = (uint32_t)((wn * 32 + nt * 8 + lr) * STRIDE_B) + kb;
                bh[nt][0] = lds32(sBh + ro);
                bh[nt][1] = lds32(sBh + ro + 16);
                bl[nt][0] = lds32(sBl + ro);
                bl[nt][1] = lds32(sBl + ro + 16);
            }
#pragma unroll
            for (int mt = 0; mt < 4; mt++)
#pragma unroll
                for (int nt = 0; nt < 4; nt++) {
                    mma16816(acc[mt][nt], ah[mt], bh[nt]);
                    mma16816(acc[mt][nt], ah[mt], bl[nt]);
                    mma16816(acc[mt][nt], al[mt], bh[nt]);
                }
        }
        __syncthreads();
        stage ^= 1;
    }

    // Epilogue: D m16n8 layout -> c0,c1 at (row=lr, col=lc2), c2,c3 at row+8
#pragma unroll
    for (int mt = 0; mt < 4; mt++) {
        const int row = bm + wm * 64 + mt * 16 + lr;
#pragma unroll
        for (int nt = 0; nt < 4; nt++) {
            const int col = bn + wn * 32 + nt * 8 + lc2;
            *(float2*)(C + (size_t)row * N + col) =
                make_float2(acc[mt][nt][0], acc[mt][nt][1]);
            *(float2*)(C + (size_t)(row + 8) * N + col) =
                make_float2(acc[mt][nt][2], acc[mt][nt][3]);
        }
    }
}

// ---------------------------------------------------------------------------
// Flash attention, fp32 (unchanged compute; epilogue emits bf16 hi/lo split)
// ---------------------------------------------------------------------------
__global__ void __launch_bounds__(256)
flash_attn(const float* __restrict__ qkv,
           __nv_bfloat16* __restrict__ oh, __nv_bfloat16* __restrict__ ol)
{
    __shared__ float Qs[64][DH + 1];
    __shared__ float Ks[32][DH + 1];
    __shared__ float Vs[32][DH];
    __shared__ float Ps[64][33];

    const int tid = threadIdx.x;
    const int b   = blockIdx.y >> 4;
    const int h   = blockIdx.y & 15;
    const int n0  = blockIdx.x * 64;
    const int ty  = tid >> 4;
    const int tx  = tid & 15;

    const size_t base = ((size_t)b * NSEQ) * QKVN + (size_t)h * DH;

#pragma unroll
    for (int p = 0; p < 4; p++) {
        int f = tid + p * 256;
        int r = f >> 4;
        int c = (f & 15) << 2;
        float4 v = *(const float4*)(qkv + base + (size_t)(n0 + r) * QKVN + c);
        Qs[r][c] = v.x; Qs[r][c + 1] = v.y; Qs[r][c + 2] = v.z; Qs[r][c + 3] = v.w;
    }

    const float NEG_INF = __int_as_float(0xff800000);
    float m_run[4], l_run[4], o[4][4];
#pragma unroll
    for (int i = 0; i < 4; i++) {
        m_run[i] = NEG_INF;
        l_run[i] = 0.f;
#pragma unroll
        for (int j = 0; j < 4; j++) o[i][j] = 0.f;
    }

    for (int kv0 = 0; kv0 < NSEQ; kv0 += 32) {
        __syncthreads();
#pragma unroll
        for (int p = 0; p < 2; p++) {
            int f = tid + p * 256;
            int r = f >> 4;
            int c = (f & 15) << 2;
            const float* rowp = qkv + base + (size_t)(kv0 + r) * QKVN;
            float4 kv4 = *(const float4*)(rowp + DIMC + c);
            Ks[r][c] = kv4.x; Ks[r][c + 1] = kv4.y; Ks[r][c + 2] = kv4.z; Ks[r][c + 3] = kv4.w;
            float4 vv = *(const float4*)(rowp + 2 * DIMC + c);
            *(float4*)&Vs[r][c] = vv;
        }
        __syncthreads();

        float s[4][2] = {{0.f, 0.f}, {0.f, 0.f}, {0.f, 0.f}, {0.f, 0.f}};
#pragma unroll 16
        for (int d = 0; d < DH; d++) {
            float b0 = Ks[2 * tx][d];
            float b1 = Ks[2 * tx + 1][d];
#pragma unroll
            for (int i = 0; i < 4; i++) {
                float a = Qs[4 * ty + i][d];
                s[i][0] += a * b0;
                s[i][1] += a * b1;
            }
        }

        float mt[4], pj[4][2], rs[4], corr[4];
#pragma unroll
        for (int i = 0; i < 4; i++) {
            s[i][0] *= SCALE; s[i][1] *= SCALE;
            mt[i] = fmaxf(s[i][0], s[i][1]);
            mt[i] = fmaxf(mt[i], __shfl_xor_sync(0xffffffffu, mt[i], 1));
            mt[i] = fmaxf(mt[i], __shfl_xor_sync(0xffffffffu, mt[i], 2));
            mt[i] = fmaxf(mt[i], __shfl_xor_sync(0xffffffffu, mt[i], 4));
            mt[i] = fmaxf(mt[i], __shfl_xor_sync(0xffffffffu, mt[i], 8));
        }
#pragma unroll
        for (int i = 0; i < 4; i++) {
            float m_new = fmaxf(m_run[i], mt[i]);
            corr[i] = __expf(m_run[i] - m_new);
            pj[i][0] = __expf(s[i][0] - m_new);
            pj[i][1] = __expf(s[i][1] - m_new);
            rs[i] = pj[i][0] + pj[i][1];
            m_run[i] = m_new;
            rs[i] += __shfl_xor_sync(0xffffffffu, rs[i], 1);
            rs[i] += __shfl_xor_sync(0xffffffffu, rs[i], 2);
            rs[i] += __shfl_xor_sync(0xffffffffu, rs[i], 4);
            rs[i] += __shfl_xor_sync(0xffffffffu, rs[i], 8);
            l_run[i] = l_run[i] * corr[i] + rs[i];
        }

#pragma unroll
        for (int i = 0; i < 4; i++) {
            Ps[4 * ty + i][2 * tx]     = pj[i][0];
            Ps[4 * ty + i][2 * tx + 1] = pj[i][1];
        }
        __syncthreads();

#pragma unroll
        for (int i = 0; i < 4; i++)
#pragma unroll
            for (int j = 0; j < 4; j++) o[i][j] *= corr[i];

#pragma unroll 8
        for (int c = 0; c < 32; c++) {
            float vr[4];
#pragma unroll
            for (int j = 0; j < 4; j++) vr[j] = Vs[c][4 * tx + j];
#pragma unroll
            for (int i = 0; i < 4; i++) {
                float pr = Ps[4 * ty + i][c];
#pragma unroll
                for (int j = 0; j < 4; j++) o[i][j] += pr * vr[j];
            }
        }
    }

#pragma unroll
    for (int i = 0; i < 4; i++) {
        float inv = 1.f / l_run[i];
        float v0 = o[i][0] * inv, v1 = o[i][1] * inv;
        float v2 = o[i][2] * inv, v3 = o[i][3] * inv;
        __nv_bfloat16 h0 = __float2bfloat16(v0), h1 = __float2bfloat16(v1);
        __nv_bfloat16 h2 = __float2bfloat16(v2), h3 = __float2bfloat16(v3);
        __nv_bfloat16 l0 = __float2bfloat16(v0 - __bfloat162float(h0));
        __nv_bfloat16 l1 = __float2bfloat16(v1 - __bfloat162float(h1));
        __nv_bfloat16 l2 = __float2bfloat16(v2 - __bfloat162float(h2));
        __nv_bfloat16 l3 = __float2bfloat16(v3 - __bfloat162float(h3));
        size_t off = ((size_t)b * NSEQ + n0 + 4 * ty + i) * DIMC + h * DH + 4 * tx;
        *(__nv_bfloat162*)(oh + off)     = __halves2bfloat162(h0, h1);
        *(__nv_bfloat162*)(oh + off + 2) = __halves2bfloat162(h2, h3);
        *(__nv_bfloat162*)(ol + off)     = __halves2bfloat162(l0, l1);
        *(__nv_bfloat162*)(ol + off + 2) = __halves2bfloat162(l2, l3);
    }
}

// ---------------------------------------------------------------------------
extern "C" void kernel_launch(void* const* d_in, const int* in_sizes, int n_in,
                              void* d_out, int out_size)
{
    (void)in_sizes; (void)n_in; (void)out_size;
    const float* x      = (const float*)d_in[0];
    const float* w_qkv  = (const float*)d_in[1];
    const float* w_proj = (const float*)d_in[2];
    float* out = (float*)d_out;

    float* qkv_p;
    __nv_bfloat16 *xh, *xl, *wqh, *wql, *wph, *wpl, *ah, *al;
    cudaGetSymbolAddress((void**)&qkv_p, g_qkv);
    cudaGetSymbolAddress((void**)&xh, g_xh);   cudaGetSymbolAddress((void**)&xl, g_xl);
    cudaGetSymbolAddress((void**)&wqh, g_wqh); cudaGetSymbolAddress((void**)&wql, g_wql);
    cudaGetSymbolAddress((void**)&wph, g_wph); cudaGetSymbolAddress((void**)&wpl, g_wpl);
    cudaGetSymbolAddress((void**)&ah, g_ah);   cudaGetSymbolAddress((void**)&al, g_al);

    const int SMEM_SZ = 2 * STAGE_SZ;   // 81920
    static int cfg_done = 0;
    if (!cfg_done) {
        cudaFuncSetAttribute(gemm_hmma, cudaFuncAttributeMaxDynamicSharedMemorySize, SMEM_SZ);
        cfg_done = 1;
    }

    // 0) split inputs to bf16 hi/lo
    {
        int n4 = MT * DIMC / 4;
        split_bf16<<<(n4 + 255) / 256, 256>>>((const float4*)x, xh, xl, n4);
        n4 = QKVN * DIMC / 4;
        split_bf16<<<(n4 + 255) / 256, 256>>>((const float4*)w_qkv, wqh, wql, n4);
        n4 = DIMC * DIMC / 4;
        split_bf16<<<(n4 + 255) / 256, 256>>>((const float4*)w_proj, wph, wpl, n4);
    }

    // 1) QKV projection: [8192,3072] = x @ w_qkv^T
    gemm_hmma<<<dim3(QKVN / 128, MT / 128), 256, SMEM_SZ>>>(xh, xl, wqh, wql,
                                                            qkv_p, MT, QKVN, DIMC);

    // 2) Attention
    flash_attn<<<dim3(NSEQ / 64, NB * NH), 256>>>(qkv_p, ah, al);

    // 3) Output projection: [8192,1024] = attn @ w_proj^T
    gemm_hmma<<<dim3(DIMC / 128, MT / 128), 256, SMEM_SZ>>>(ah, al, wph, wpl,
                                                            out, MT, DIMC, DIMC);
}

// round 4
// speedup vs baseline: 2.5080x; 2.0067x over previous
#include <cuda_runtime.h>
#include <cuda_bf16.h>
#include <cstdint>

#define DIMC 1024
#define NB   4
#define NSEQ 2048
#define NH   16
#define DH   64
#define MT   (NB * NSEQ)      // 8192 rows
#define QKVN (3 * DIMC)       // 3072
#define SCALE 0.125f          // 64^-0.5

// ---------------- scratch (static device globals: allocation-free) ----------
__device__ __nv_bfloat16 g_qkvh[(size_t)MT * QKVN];   // qkv split hi/lo
__device__ __nv_bfloat16 g_qkvl[(size_t)MT * QKVN];
__device__ __nv_bfloat16 g_xh[(size_t)MT * DIMC];
__device__ __nv_bfloat16 g_xl[(size_t)MT * DIMC];
__device__ __nv_bfloat16 g_wqh[(size_t)QKVN * DIMC];
__device__ __nv_bfloat16 g_wql[(size_t)QKVN * DIMC];
__device__ __nv_bfloat16 g_wph[(size_t)DIMC * DIMC];
__device__ __nv_bfloat16 g_wpl[(size_t)DIMC * DIMC];
__device__ __nv_bfloat16 g_ah[(size_t)MT * DIMC];
__device__ __nv_bfloat16 g_al[(size_t)MT * DIMC];

// ---------------- PTX helpers (baseline ISA: mma.sync / ldmatrix / cp.async) -
__device__ __forceinline__ uint32_t smem_u32_of(const void* p) {
    uint32_t a;
    asm("{ .reg .u64 t; cvta.to.shared.u64 t, %1; cvt.u32.u64 %0, t; }"
        : "=r"(a) : "l"(p));
    return a;
}
__device__ __forceinline__ void cp16(uint32_t dst, const void* src) {
    asm volatile("cp.async.cg.shared.global [%0], [%1], 16;" :: "r"(dst), "l"(src));
}
#define CP_COMMIT() asm volatile("cp.async.commit_group;" ::: "memory")
#define CP_WAIT(n)  asm volatile("cp.async.wait_group %0;" :: "n"(n) : "memory")

__device__ __forceinline__ uint32_t lds32(uint32_t a) {
    uint32_t v;
    asm volatile("ld.shared.b32 %0, [%1];" : "=r"(v) : "r"(a));
    return v;
}
__device__ __forceinline__ void ldsm4(uint32_t* r, uint32_t a) {
    asm volatile("ldmatrix.sync.aligned.m8n8.x4.shared.b16 {%0,%1,%2,%3}, [%4];"
                 : "=r"(r[0]), "=r"(r[1]), "=r"(r[2]), "=r"(r[3]) : "r"(a));
}
__device__ __forceinline__ void ldsm4t(uint32_t* r, uint32_t a) {
    asm volatile("ldmatrix.sync.aligned.m8n8.x4.trans.shared.b16 {%0,%1,%2,%3}, [%4];"
                 : "=r"(r[0]), "=r"(r[1]), "=r"(r[2]), "=r"(r[3]) : "r"(a));
}
__device__ __forceinline__ void mma16816(float* d, const uint32_t* a, const uint32_t* b) {
    asm volatile(
        "mma.sync.aligned.m16n8k16.row.col.f32.bf16.bf16.f32 "
        "{%0,%1,%2,%3}, {%4,%5,%6,%7}, {%8,%9}, {%0,%1,%2,%3};"
        : "+f"(d[0]), "+f"(d[1]), "+f"(d[2]), "+f"(d[3])
        : "r"(a[0]), "r"(a[1]), "r"(a[2]), "r"(a[3]), "r"(b[0]), "r"(b[1]));
}
__device__ __forceinline__ void mma_b(float* d, const uint32_t* a, uint32_t b0, uint32_t b1) {
    asm volatile(
        "mma.sync.aligned.m16n8k16.row.col.f32.bf16.bf16.f32 "
        "{%0,%1,%2,%3}, {%4,%5,%6,%7}, {%8,%9}, {%0,%1,%2,%3};"
        : "+f"(d[0]), "+f"(d[1]), "+f"(d[2]), "+f"(d[3])
        : "r"(a[0]), "r"(a[1]), "r"(a[2]), "r"(a[3]), "r"(b0), "r"(b1));
}
// split pair of fp32 into packed bf16x2 hi and lo
__device__ __forceinline__ void split2(float x, float y, uint32_t& hi, uint32_t& lo) {
    __nv_bfloat16 hx = __float2bfloat16(x), hy = __float2bfloat16(y);
    __nv_bfloat16 lx = __float2bfloat16(x - __bfloat162float(hx));
    __nv_bfloat16 ly = __float2bfloat16(y - __bfloat162float(hy));
    __nv_bfloat162 th = __halves2bfloat162(hx, hy);
    __nv_bfloat162 tl = __halves2bfloat162(lx, ly);
    hi = *(uint32_t*)&th;
    lo = *(uint32_t*)&tl;
}

// ---------------------------------------------------------------------------
// split fp32 -> bf16 hi/lo
// ---------------------------------------------------------------------------
__global__ void __launch_bounds__(256)
split_bf16(const float4* __restrict__ src, __nv_bfloat16* __restrict__ hi,
           __nv_bfloat16* __restrict__ lo, int n4)
{
    int i = blockIdx.x * blockDim.x + threadIdx.x;
    if (i >= n4) return;
    float4 v = src[i];
    uint32_t h0, l0, h1, l1;
    split2(v.x, v.y, h0, l0);
    split2(v.z, v.w, h1, l1);
    size_t o = (size_t)i * 4;
    *(uint32_t*)(hi + o)     = h0;
    *(uint32_t*)(hi + o + 2) = h1;
    *(uint32_t*)(lo + o)     = l0;
    *(uint32_t*)(lo + o + 2) = l1;
}

// ---------------------------------------------------------------------------
// Split-bf16 HMMA GEMM NT: C = (Ah+Al)[M,K] * (Bh+Bl)[N,K]^T
// Output: fp32 C (if Ch==null) or split hi/lo bf16 (Ch,Cl).
// ---------------------------------------------------------------------------
#define STRIDE_B 80
#define ARR_SZ   (128 * STRIDE_B)
#define STAGE_SZ (4 * ARR_SZ)

__global__ void __launch_bounds__(256, 1)
gemm_hmma(const __nv_bfloat16* __restrict__ Ah, const __nv_bfloat16* __restrict__ Al,
          const __nv_bfloat16* __restrict__ Bh, const __nv_bfloat16* __restrict__ Bl,
          float* __restrict__ C, __nv_bfloat16* __restrict__ Ch,
          __nv_bfloat16* __restrict__ Cl, int M, int N, int K)
{
    extern __shared__ __align__(16) char dsm[];
    const uint32_t sb = smem_u32_of(dsm);

    const int tid  = threadIdx.x;
    const int wid  = tid >> 5;
    const int lane = tid & 31;
    const int wm   = wid & 1;
    const int wn   = wid >> 1;
    const int bm   = blockIdx.y * 128;
    const int bn   = blockIdx.x * 128;
    const int lr   = lane >> 2;
    const int lc2  = (lane & 3) * 2;

    const int r0 = (tid * 2) >> 2, c0 = (tid * 2) & 3;
    const int r1 = (tid * 2 + 1) >> 2, c1 = (tid * 2 + 1) & 3;

    float acc[4][4][4];
#pragma unroll
    for (int i = 0; i < 4; i++)
#pragma unroll
        for (int j = 0; j < 4; j++)
#pragma unroll
            for (int k = 0; k < 4; k++) acc[i][j][k] = 0.f;

    const int nk = K >> 5;

    auto issue = [&](int chunk, int stage) {
        const int k0 = chunk << 5;
        const uint32_t s = sb + stage * STAGE_SZ;
        const size_t ga0 = (size_t)(bm + r0) * K + k0 + c0 * 8;
        const size_t ga1 = (size_t)(bm + r1) * K + k0 + c1 * 8;
        const size_t gb0 = (size_t)(bn + r0) * K + k0 + c0 * 8;
        const size_t gb1 = (size_t)(bn + r1) * K + k0 + c1 * 8;
        const uint32_t so0 = (uint32_t)(r0 * STRIDE_B + c0 * 16);
        const uint32_t so1 = (uint32_t)(r1 * STRIDE_B + c1 * 16);
        cp16(s + so0,              Ah + ga0);
        cp16(s + so1,              Ah + ga1);
        cp16(s + ARR_SZ + so0,     Al + ga0);
        cp16(s + ARR_SZ + so1,     Al + ga1);
        cp16(s + 2 * ARR_SZ + so0, Bh + gb0);
        cp16(s + 2 * ARR_SZ + so1, Bh + gb1);
        cp16(s + 3 * ARR_SZ + so0, Bl + gb0);
        cp16(s + 3 * ARR_SZ + so1, Bl + gb1);
    };

    issue(0, 0);
    CP_COMMIT();

    int stage = 0;
    for (int ch = 0; ch < nk; ch++) {
        if (ch + 1 < nk) {
            issue(ch + 1, stage ^ 1);
            CP_COMMIT();
            CP_WAIT(1);
        } else {
            CP_WAIT(0);
        }
        __syncthreads();

        const uint32_t sAh = sb + stage * STAGE_SZ;
        const uint32_t sAl = sAh + ARR_SZ;
        const uint32_t sBh = sAh + 2 * ARR_SZ;
        const uint32_t sBl = sAh + 3 * ARR_SZ;

#pragma unroll
        for (int ks = 0; ks < 2; ks++) {
            const uint32_t kb = (uint32_t)((ks * 16 + lc2) * 2);
            uint32_t ah[4][4], al[4][4], bh[4][2], bl[4][2];
#pragma unroll
            for (int mt = 0; mt < 4; mt++) {
                uint32_t ro = (uint32_t)((wm * 64 + mt * 16 + lr) * STRIDE_B) + kb;
                ah[mt][0] = lds32(sAh + ro);
                ah[mt][1] = lds32(sAh + ro + 8 * STRIDE_B);
                ah[mt][2] = lds32(sAh + ro + 16);
                ah[mt][3] = lds32(sAh + ro + 8 * STRIDE_B + 16);
                al[mt][0] = lds32(sAl + ro);
                al[mt][1] = lds32(sAl + ro + 8 * STRIDE_B);
                al[mt][2] = lds32(sAl + ro + 16);
                al[mt][3] = lds32(sAl + ro + 8 * STRIDE_B + 16);
            }
#pragma unroll
            for (int nt = 0; nt < 4; nt++) {
                uint32_t ro = (uint32_t)((wn * 32 + nt * 8 + lr) * STRIDE_B) + kb;
                bh[nt][0] = lds32(sBh + ro);
                bh[nt][1] = lds32(sBh + ro + 16);
                bl[nt][0] = lds32(sBl + ro);
                bl[nt][1] = lds32(sBl + ro + 16);
            }
#pragma unroll
            for (int mt = 0; mt < 4; mt++)
#pragma unroll
                for (int nt = 0; nt < 4; nt++) {
                    mma16816(acc[mt][nt], ah[mt], bh[nt]);
                    mma16816(acc[mt][nt], ah[mt], bl[nt]);
                    mma16816(acc[mt][nt], al[mt], bh[nt]);
                }
        }
        __syncthreads();
        stage ^= 1;
    }

    if (Ch == nullptr) {
#pragma unroll
        for (int mt = 0; mt < 4; mt++) {
            const int row = bm + wm * 64 + mt * 16 + lr;
#pragma unroll
            for (int nt = 0; nt < 4; nt++) {
                const int col = bn + wn * 32 + nt * 8 + lc2;
                *(float2*)(C + (size_t)row * N + col) =
                    make_float2(acc[mt][nt][0], acc[mt][nt][1]);
                *(float2*)(C + (size_t)(row + 8) * N + col) =
                    make_float2(acc[mt][nt][2], acc[mt][nt][3]);
            }
        }
    } else {
#pragma unroll
        for (int mt = 0; mt < 4; mt++) {
            const int row = bm + wm * 64 + mt * 16 + lr;
#pragma unroll
            for (int nt = 0; nt < 4; nt++) {
                const int col = bn + wn * 32 + nt * 8 + lc2;
                uint32_t h0, l0, h1, l1;
                split2(acc[mt][nt][0], acc[mt][nt][1], h0, l0);
                split2(acc[mt][nt][2], acc[mt][nt][3], h1, l1);
                *(uint32_t*)(Ch + (size_t)row * N + col)       = h0;
                *(uint32_t*)(Cl + (size_t)row * N + col)       = l0;
                *(uint32_t*)(Ch + (size_t)(row + 8) * N + col) = h1;
                *(uint32_t*)(Cl + (size_t)(row + 8) * N + col) = l1;
            }
        }
    }
}

// ---------------------------------------------------------------------------
// Tensor-core flash attention (split-bf16, FA2 register dataflow).
// CTA: 128 q-rows x one (b,h). 8 warps, warp = 16 q-rows. KV tiles of 64,
// double-buffered. S and PV both split-bf16 (3 MMAs each).
// ---------------------------------------------------------------------------
#define AT_STRIDE 144                      // 128B data + 16B pad
#define QARR  (128 * AT_STRIDE)            // 18432
#define KVARR (64 * AT_STRIDE)             // 9216
#define KV_STAGE (4 * KVARR)               // 36864
#define AT_SMEM (2 * QARR + 2 * KV_STAGE)  // 110592

__global__ void __launch_bounds__(256, 1)
flash_attn_tc(const __nv_bfloat16* __restrict__ qh_g,
              const __nv_bfloat16* __restrict__ ql_g,
              __nv_bfloat16* __restrict__ oh_g,
              __nv_bfloat16* __restrict__ ol_g)
{
    extern __shared__ __align__(16) char dsm[];
    const uint32_t sb  = smem_u32_of(dsm);
    const uint32_t sQh = sb, sQl = sb + QARR;
    const uint32_t sKV = sb + 2 * QARR;

    const int tid  = threadIdx.x;
    const int lane = tid & 31;
    const int wid  = tid >> 5;
    const int b    = blockIdx.y >> 4;
    const int h    = blockIdx.y & 15;
    const int n0   = blockIdx.x * 128;
    const int m0   = wid * 16;
    const int lr   = lane >> 2;
    const int lc   = lane & 3;

    const size_t rowbase = (size_t)b * NSEQ;
    const int    hoff    = h * DH;

    // per-lane ldmatrix offset patterns
    const uint32_t qa_off = (uint32_t)((m0 + (lane & 15)) * AT_STRIDE + ((lane >> 4) << 4));
    const int      k_rl   = (lane & 7) + ((lane & 16) >> 1);
    const uint32_t k_ch   = (uint32_t)(((lane >> 3) & 1) << 4);
    const int      v_rl   = (lane & 7) + (((lane >> 3) & 1) << 3);
    const uint32_t v_ch   = (uint32_t)(((lane >> 4) & 1) << 4);

    // ---- issue Q tile (once) ----
#pragma unroll
    for (int i = 0; i < 8; i++) {
        int q = tid + i * 256;
        int arr = q >> 10;                  // 0=Qh 1=Ql
        int r = (q & 1023) >> 3;
        int c = q & 7;
        const __nv_bfloat16* src = (arr ? ql_g : qh_g)
            + (rowbase + n0 + r) * QKVN + hoff + c * 8;
        cp16((arr ? sQl : sQh) + (uint32_t)(r * AT_STRIDE + c * 16), src);
    }

    auto issueKV = [&](int kv0, int stage) {
#pragma unroll
        for (int i = 0; i < 8; i++) {
            int q = tid + i * 256;
            int arr = q >> 9;               // 0=Kh 1=Kl 2=Vh 3=Vl
            int r = (q & 511) >> 3;
            int c = q & 7;
            const __nv_bfloat16* base = (arr & 1) ? ql_g : qh_g;
            int coff = ((arr >> 1) ? 2 * DIMC : DIMC) + hoff + c * 8;
            const __nv_bfloat16* src = base + (rowbase + kv0 + r) * QKVN + coff;
            cp16(sKV + (uint32_t)(stage * KV_STAGE + arr * KVARR + r * AT_STRIDE + c * 16), src);
        }
    };

    issueKV(0, 0);
    CP_COMMIT();

    const float NEG_INF = __int_as_float(0xff800000);
    float m0s = NEG_INF, m1s = NEG_INF, l0s = 0.f, l1s = 0.f;
    float o[8][4];
#pragma unroll
    for (int nt = 0; nt < 8; nt++)
#pragma unroll
        for (int j = 0; j < 4; j++) o[nt][j] = 0.f;

    int stage = 0;
    for (int it = 0; it < NSEQ / 64; it++) {
        if (it + 1 < NSEQ / 64) {
            issueKV((it + 1) * 64, stage ^ 1);
            CP_COMMIT();
            CP_WAIT(1);
        } else {
            CP_WAIT(0);
        }
        __syncthreads();

        const uint32_t sK  = sKV + (uint32_t)(stage * KV_STAGE);
        const uint32_t sKh = sK, sKl = sK + KVARR;
        const uint32_t sVh = sK + 2 * KVARR, sVl = sK + 3 * KVARR;

        // ---- S = Q K^T (split: 3 MMAs) ----
        float c[8][4];
#pragma unroll
        for (int nt = 0; nt < 8; nt++)
#pragma unroll
            for (int j = 0; j < 4; j++) c[nt][j] = 0.f;

#pragma unroll
        for (int kt = 0; kt < 4; kt++) {
            uint32_t qh4[4], ql4[4];
            ldsm4(qh4, sQh + qa_off + 32 * kt);
            ldsm4(ql4, sQl + qa_off + 32 * kt);
#pragma unroll
            for (int p = 0; p < 4; p++) {
                uint32_t kh4[4], kl4[4];
                uint32_t ko = (uint32_t)((p * 16 + k_rl) * AT_STRIDE) + k_ch + 32 * kt;
                ldsm4(kh4, sKh + ko);
                ldsm4(kl4, sKl + ko);
                mma_b(c[2 * p],     qh4, kh4[0], kh4[1]);
                mma_b(c[2 * p],     qh4, kl4[0], kl4[1]);
                mma_b(c[2 * p],     ql4, kh4[0], kh4[1]);
                mma_b(c[2 * p + 1], qh4, kh4[2], kh4[3]);
                mma_b(c[2 * p + 1], qh4, kl4[2], kl4[3]);
                mma_b(c[2 * p + 1], ql4, kh4[2], kh4[3]);
            }
        }

        // ---- online softmax (rows lr and lr+8 per thread) ----
        float mt0 = NEG_INF, mt1 = NEG_INF;
#pragma unroll
        for (int nt = 0; nt < 8; nt++) {
            c[nt][0] *= SCALE; c[nt][1] *= SCALE;
            c[nt][2] *= SCALE; c[nt][3] *= SCALE;
            mt0 = fmaxf(mt0, fmaxf(c[nt][0], c[nt][1]));
            mt1 = fmaxf(mt1, fmaxf(c[nt][2], c[nt][3]));
        }
        mt0 = fmaxf(mt0, __shfl_xor_sync(0xffffffffu, mt0, 1));
        mt0 = fmaxf(mt0, __shfl_xor_sync(0xffffffffu, mt0, 2));
        mt1 = fmaxf(mt1, __shfl_xor_sync(0xffffffffu, mt1, 1));
        mt1 = fmaxf(mt1, __shfl_xor_sync(0xffffffffu, mt1, 2));

        float mn0 = fmaxf(m0s, mt0), mn1 = fmaxf(m1s, mt1);
        float corr0 = __expf(m0s - mn0), corr1 = __expf(m1s - mn1);
        m0s = mn0; m1s = mn1;

        float rs0 = 0.f, rs1 = 0.f;
#pragma unroll
        for (int nt = 0; nt < 8; nt++) {
            c[nt][0] = __expf(c[nt][0] - mn0);
            c[nt][1] = __expf(c[nt][1] - mn0);
            c[nt][2] = __expf(c[nt][2] - mn1);
            c[nt][3] = __expf(c[nt][3] - mn1);
            rs0 += c[nt][0] + c[nt][1];
            rs1 += c[nt][2] + c[nt][3];
        }
        rs0 += __shfl_xor_sync(0xffffffffu, rs0, 1);
        rs0 += __shfl_xor_sync(0xffffffffu, rs0, 2);
        rs1 += __shfl_xor_sync(0xffffffffu, rs1, 1);
        rs1 += __shfl_xor_sync(0xffffffffu, rs1, 2);
        l0s = l0s * corr0 + rs0;
        l1s = l1s * corr1 + rs1;

        // ---- pack P fragments (A operand of PV) from S d-frags ----
        uint32_t aph[4][4], apl[4][4];
#pragma unroll
        for (int kt = 0; kt < 4; kt++) {
            split2(c[2 * kt][0],     c[2 * kt][1],     aph[kt][0], apl[kt][0]);
            split2(c[2 * kt][2],     c[2 * kt][3],     aph[kt][1], apl[kt][1]);
            split2(c[2 * kt + 1][0], c[2 * kt + 1][1], aph[kt][2], apl[kt][2]);
            split2(c[2 * kt + 1][2], c[2 * kt + 1][3], aph[kt][3], apl[kt][3]);
        }

        // ---- rescale O ----
#pragma unroll
        for (int nt = 0; nt < 8; nt++) {
            o[nt][0] *= corr0; o[nt][1] *= corr0;
            o[nt][2] *= corr1; o[nt][3] *= corr1;
        }

        // ---- O += P V (split: 3 MMAs) ----
#pragma unroll
        for (int kt = 0; kt < 4; kt++) {
#pragma unroll
            for (int g = 0; g < 4; g++) {
                uint32_t vh4[4], vl4[4];
                uint32_t vo = (uint32_t)((16 * kt + v_rl) * AT_STRIDE) + 32 * g + v_ch;
                ldsm4t(vh4, sVh + vo);
                ldsm4t(vl4, sVl + vo);
                mma_b(o[2 * g],     aph[kt], vh4[0], vh4[1]);
                mma_b(o[2 * g],     aph[kt], vl4[0], vl4[1]);
                mma_b(o[2 * g],     apl[kt], vh4[0], vh4[1]);
                mma_b(o[2 * g + 1], aph[kt], vh4[2], vh4[3]);
                mma_b(o[2 * g + 1], aph[kt], vl4[2], vl4[3]);
                mma_b(o[2 * g + 1], apl[kt], vh4[2], vh4[3]);
            }
        }
        __syncthreads();
        stage ^= 1;
    }

    // ---- epilogue: normalize, split hi/lo, store ----
    const float inv0 = 1.f / l0s, inv1 = 1.f / l1s;
    const size_t r0 = rowbase + n0 + m0 + lr;
    const size_t r1 = r0 + 8;
#pragma unroll
    for (int nt = 0; nt < 8; nt++) {
        const int col = hoff + nt * 8 + 2 * lc;
        uint32_t h0, l0, h1, l1;
        split2(o[nt][0] * inv0, o[nt][1] * inv0, h0, l0);
        split2(o[nt][2] * inv1, o[nt][3] * inv1, h1, l1);
        *(uint32_t*)(oh_g + r0 * DIMC + col) = h0;
        *(uint32_t*)(ol_g + r0 * DIMC + col) = l0;
        *(uint32_t*)(oh_g + r1 * DIMC + col) = h1;
        *(uint32_t*)(ol_g + r1 * DIMC + col) = l1;
    }
}

// ---------------------------------------------------------------------------
extern "C" void kernel_launch(void* const* d_in, const int* in_sizes, int n_in,
                              void* d_out, int out_size)
{
    (void)in_sizes; (void)n_in; (void)out_size;
    const float* x      = (const float*)d_in[0];
    const float* w_qkv  = (const float*)d_in[1];
    const float* w_proj = (const float*)d_in[2];
    float* out = (float*)d_out;

    __nv_bfloat16 *qh, *ql, *xh, *xl, *wqh, *wql, *wph, *wpl, *ah, *al;
    cudaGetSymbolAddress((void**)&qh, g_qkvh); cudaGetSymbolAddress((void**)&ql, g_qkvl);
    cudaGetSymbolAddress((void**)&xh, g_xh);   cudaGetSymbolAddress((void**)&xl, g_xl);
    cudaGetSymbolAddress((void**)&wqh, g_wqh); cudaGetSymbolAddress((void**)&wql, g_wql);
    cudaGetSymbolAddress((void**)&wph, g_wph); cudaGetSymbolAddress((void**)&wpl, g_wpl);
    cudaGetSymbolAddress((void**)&ah, g_ah);   cudaGetSymbolAddress((void**)&al, g_al);

    const int GEMM_SMEM = 2 * STAGE_SZ;   // 81920
    static int cfg_done = 0;
    if (!cfg_done) {
        cudaFuncSetAttribute(gemm_hmma, cudaFuncAttributeMaxDynamicSharedMemorySize, GEMM_SMEM);
        cudaFuncSetAttribute(flash_attn_tc, cudaFuncAttributeMaxDynamicSharedMemorySize, AT_SMEM);
        cfg_done = 1;
    }

    // 0) split inputs to bf16 hi/lo
    {
        int n4 = MT * DIMC / 4;
        split_bf16<<<(n4 + 255) / 256, 256>>>((const float4*)x, xh, xl, n4);
        n4 = QKVN * DIMC / 4;
        split_bf16<<<(n4 + 255) / 256, 256>>>((const float4*)w_qkv, wqh, wql, n4);
        n4 = DIMC * DIMC / 4;
        split_bf16<<<(n4 + 255) / 256, 256>>>((const float4*)w_proj, wph, wpl, n4);
    }

    // 1) QKV projection -> split hi/lo bf16 qkv
    gemm_hmma<<<dim3(QKVN / 128, MT / 128), 256, GEMM_SMEM>>>(
        xh, xl, wqh, wql, nullptr, qh, ql, MT, QKVN, DIMC);

    // 2) Tensor-core flash attention
    flash_attn_tc<<<dim3(NSEQ / 128, NB * NH), 256, AT_SMEM>>>(qh, ql, ah, al);

    // 3) Output projection -> fp32 out
    gemm_hmma<<<dim3(DIMC / 128, MT / 128), 256, GEMM_SMEM>>>(
        ah, al, wph, wpl, out, nullptr, nullptr, MT, DIMC, DIMC);
}

// round 5
// speedup vs baseline: 2.5350x; 1.0108x over previous
#include <cuda_runtime.h>
#include <cuda_bf16.h>
#include <cstdint>

#define DIMC 1024
#define NB   4
#define NSEQ 2048
#define NH   16
#define DH   64
#define MT   (NB * NSEQ)      // 8192 rows
#define QKVN (3 * DIMC)       // 3072
#define SCALE 0.125f          // 64^-0.5

// ---------------- scratch (static device globals: allocation-free) ----------
__device__ __nv_bfloat16 g_qkvh[(size_t)MT * QKVN];   // qkv split hi/lo
__device__ __nv_bfloat16 g_qkvl[(size_t)MT * QKVN];
__device__ __nv_bfloat16 g_xh[(size_t)MT * DIMC];
__device__ __nv_bfloat16 g_xl[(size_t)MT * DIMC];
__device__ __nv_bfloat16 g_wqh[(size_t)QKVN * DIMC];
__device__ __nv_bfloat16 g_wql[(size_t)QKVN * DIMC];
__device__ __nv_bfloat16 g_wph[(size_t)DIMC * DIMC];
__device__ __nv_bfloat16 g_wpl[(size_t)DIMC * DIMC];
__device__ __nv_bfloat16 g_ah[(size_t)MT * DIMC];
__device__ __nv_bfloat16 g_al[(size_t)MT * DIMC];

// ---------------- PTX helpers (baseline ISA: mma.sync / ldmatrix / cp.async) -
__device__ __forceinline__ uint32_t smem_u32_of(const void* p) {
    uint32_t a;
    asm("{ .reg .u64 t; cvta.to.shared.u64 t, %1; cvt.u32.u64 %0, t; }"
        : "=r"(a) : "l"(p));
    return a;
}
__device__ __forceinline__ void cp16(uint32_t dst, const void* src) {
    asm volatile("cp.async.cg.shared.global [%0], [%1], 16;" :: "r"(dst), "l"(src));
}
#define CP_COMMIT() asm volatile("cp.async.commit_group;" ::: "memory")
#define CP_WAIT(n)  asm volatile("cp.async.wait_group %0;" :: "n"(n) : "memory")

__device__ __forceinline__ void ldsm4(uint32_t* r, uint32_t a) {
    asm volatile("ldmatrix.sync.aligned.m8n8.x4.shared.b16 {%0,%1,%2,%3}, [%4];"
                 : "=r"(r[0]), "=r"(r[1]), "=r"(r[2]), "=r"(r[3]) : "r"(a));
}
__device__ __forceinline__ void ldsm4t(uint32_t* r, uint32_t a) {
    asm volatile("ldmatrix.sync.aligned.m8n8.x4.trans.shared.b16 {%0,%1,%2,%3}, [%4];"
                 : "=r"(r[0]), "=r"(r[1]), "=r"(r[2]), "=r"(r[3]) : "r"(a));
}
__device__ __forceinline__ void mma_b(float* d, const uint32_t* a, uint32_t b0, uint32_t b1) {
    asm volatile(
        "mma.sync.aligned.m16n8k16.row.col.f32.bf16.bf16.f32 "
        "{%0,%1,%2,%3}, {%4,%5,%6,%7}, {%8,%9}, {%0,%1,%2,%3};"
        : "+f"(d[0]), "+f"(d[1]), "+f"(d[2]), "+f"(d[3])
        : "r"(a[0]), "r"(a[1]), "r"(a[2]), "r"(a[3]), "r"(b0), "r"(b1));
}
// split pair of fp32 into packed bf16x2 hi and lo
__device__ __forceinline__ void split2(float x, float y, uint32_t& hi, uint32_t& lo) {
    __nv_bfloat16 hx = __float2bfloat16(x), hy = __float2bfloat16(y);
    __nv_bfloat16 lx = __float2bfloat16(x - __bfloat162float(hx));
    __nv_bfloat16 ly = __float2bfloat16(y - __bfloat162float(hy));
    __nv_bfloat162 th = __halves2bfloat162(hx, hy);
    __nv_bfloat162 tl = __halves2bfloat162(lx, ly);
    hi = *(uint32_t*)&th;
    lo = *(uint32_t*)&tl;
}

// ---------------------------------------------------------------------------
// split fp32 -> bf16 hi/lo
// ---------------------------------------------------------------------------
__global__ void __launch_bounds__(256)
split_bf16(const float4* __restrict__ src, __nv_bfloat16* __restrict__ hi,
           __nv_bfloat16* __restrict__ lo, int n4)
{
    int i = blockIdx.x * blockDim.x + threadIdx.x;
    if (i >= n4) return;
    float4 v = src[i];
    uint32_t h0, l0, h1, l1;
    split2(v.x, v.y, h0, l0);
    split2(v.z, v.w, h1, l1);
    size_t o = (size_t)i * 4;
    *(uint32_t*)(hi + o)     = h0;
    *(uint32_t*)(hi + o + 2) = h1;
    *(uint32_t*)(lo + o)     = l0;
    *(uint32_t*)(lo + o + 2) = l1;
}

// ---------------------------------------------------------------------------
// Split-bf16 HMMA GEMM NT: C = (Ah+Al)[M,K] * (Bh+Bl)[N,K]^T
// 128x128 CTA tile, BK=32, 8 warps (2x4), warp tile 64x32.
// ldmatrix.x4 fragment loads; 3-stage cp.async, depth-2 prefetch,
// one barrier per chunk. Output fp32 C (Ch==null) or split hi/lo (Ch,Cl).
// ---------------------------------------------------------------------------
#define STRIDE_B 80
#define ARR_SZ   (128 * STRIDE_B)        // 10240
#define STAGE_SZ (4 * ARR_SZ)            // 40960
#define GSMEM    (3 * STAGE_SZ)          // 122880

__global__ void __launch_bounds__(256, 1)
gemm_hmma(const __nv_bfloat16* __restrict__ Ah, const __nv_bfloat16* __restrict__ Al,
          const __nv_bfloat16* __restrict__ Bh, const __nv_bfloat16* __restrict__ Bl,
          float* __restrict__ C, __nv_bfloat16* __restrict__ Ch,
          __nv_bfloat16* __restrict__ Cl, int M, int N, int K)
{
    extern __shared__ __align__(16) char dsm[];
    const uint32_t sb = smem_u32_of(dsm);

    const int tid  = threadIdx.x;
    const int wid  = tid >> 5;
    const int lane = tid & 31;
    const int wm   = wid & 1;
    const int wn   = wid >> 1;
    const int bm   = blockIdx.y * 128;
    const int bn   = blockIdx.x * 128;
    const int lr   = lane >> 2;
    const int lc2  = (lane & 3) * 2;

    // cp.async mapping: 512 16B-chunks per array per stage; 2 per thread
    const int r0 = (tid * 2) >> 2, c0 = (tid * 2) & 3;
    const int r1 = (tid * 2 + 1) >> 2, c1 = (tid * 2 + 1) & 3;

    // ldmatrix lane patterns (identical to the validated attention kernel)
    const uint32_t a_off = (uint32_t)((wm * 64 + (lane & 15)) * STRIDE_B + ((lane >> 4) << 4));
    const int      k_rl  = (lane & 7) + ((lane & 16) >> 1);   // B rows within 16
    const uint32_t k_ch  = (uint32_t)(((lane >> 3) & 1) << 4);

    float acc[4][4][4];
#pragma unroll
    for (int i = 0; i < 4; i++)
#pragma unroll
        for (int j = 0; j < 4; j++)
#pragma unroll
            for (int k = 0; k < 4; k++) acc[i][j][k] = 0.f;

    const int nk = K >> 5;

    auto issue = [&](int chunk, int stage) {
        const int k0 = chunk << 5;
        const uint32_t s = sb + stage * STAGE_SZ;
        const size_t ga0 = (size_t)(bm + r0) * K + k0 + c0 * 8;
        const size_t ga1 = (size_t)(bm + r1) * K + k0 + c1 * 8;
        const size_t gb0 = (size_t)(bn + r0) * K + k0 + c0 * 8;
        const size_t gb1 = (size_t)(bn + r1) * K + k0 + c1 * 8;
        const uint32_t so0 = (uint32_t)(r0 * STRIDE_B + c0 * 16);
        const uint32_t so1 = (uint32_t)(r1 * STRIDE_B + c1 * 16);
        cp16(s + so0,              Ah + ga0);
        cp16(s + so1,              Ah + ga1);
        cp16(s + ARR_SZ + so0,     Al + ga0);
        cp16(s + ARR_SZ + so1,     Al + ga1);
        cp16(s + 2 * ARR_SZ + so0, Bh + gb0);
        cp16(s + 2 * ARR_SZ + so1, Bh + gb1);
        cp16(s + 3 * ARR_SZ + so0, Bl + gb0);
        cp16(s + 3 * ARR_SZ + so1, Bl + gb1);
    };

    issue(0, 0);
    CP_COMMIT();
    if (nk > 1) { issue(1, 1); CP_COMMIT(); }

    int stage = 0;
    for (int ch = 0; ch < nk; ch++) {
        if (ch + 1 < nk) { CP_WAIT(1); } else { CP_WAIT(0); }
        __syncthreads();     // all warps done reading stage (ch-1)%3; ch visible
        if (ch + 2 < nk) {
            int ws = stage + 2; if (ws >= 3) ws -= 3;
            issue(ch + 2, ws);
            CP_COMMIT();
        }

        const uint32_t sAh = sb + stage * STAGE_SZ;
        const uint32_t sAl = sAh + ARR_SZ;
        const uint32_t sBh = sAh + 2 * ARR_SZ;
        const uint32_t sBl = sAh + 3 * ARR_SZ;

#pragma unroll
        for (int ks = 0; ks < 2; ks++) {
            const uint32_t kb = (uint32_t)(ks * 32);
            uint32_t ah[4][4], al[4][4], bh[2][4], bl[2][4];
#pragma unroll
            for (int mt = 0; mt < 4; mt++) {
                uint32_t ro = a_off + (uint32_t)(mt * 16 * STRIDE_B) + kb;
                ldsm4(ah[mt], sAh + ro);
                ldsm4(al[mt], sAl + ro);
            }
#pragma unroll
            for (int nt2 = 0; nt2 < 2; nt2++) {
                uint32_t ro = (uint32_t)((wn * 32 + nt2 * 16 + k_rl) * STRIDE_B) + k_ch + kb;
                ldsm4(bh[nt2], sBh + ro);
                ldsm4(bl[nt2], sBl + ro);
            }
#pragma unroll
            for (int mt = 0; mt < 4; mt++)
#pragma unroll
                for (int nt2 = 0; nt2 < 2; nt2++) {
                    float* d0 = acc[mt][nt2 * 2];
                    float* d1 = acc[mt][nt2 * 2 + 1];
                    mma_b(d0, ah[mt], bh[nt2][0], bh[nt2][1]);
                    mma_b(d0, ah[mt], bl[nt2][0], bl[nt2][1]);
                    mma_b(d0, al[mt], bh[nt2][0], bh[nt2][1]);
                    mma_b(d1, ah[mt], bh[nt2][2], bh[nt2][3]);
                    mma_b(d1, ah[mt], bl[nt2][2], bl[nt2][3]);
                    mma_b(d1, al[mt], bh[nt2][2], bh[nt2][3]);
                }
        }
        stage++; if (stage >= 3) stage = 0;
    }

    if (Ch == nullptr) {
#pragma unroll
        for (int mt = 0; mt < 4; mt++) {
            const int row = bm + wm * 64 + mt * 16 + lr;
#pragma unroll
            for (int nt = 0; nt < 4; nt++) {
                const int col = bn + wn * 32 + nt * 8 + lc2;
                *(float2*)(C + (size_t)row * N + col) =
                    make_float2(acc[mt][nt][0], acc[mt][nt][1]);
                *(float2*)(C + (size_t)(row + 8) * N + col) =
                    make_float2(acc[mt][nt][2], acc[mt][nt][3]);
            }
        }
    } else {
#pragma unroll
        for (int mt = 0; mt < 4; mt++) {
            const int row = bm + wm * 64 + mt * 16 + lr;
#pragma unroll
            for (int nt = 0; nt < 4; nt++) {
                const int col = bn + wn * 32 + nt * 8 + lc2;
                uint32_t h0, l0, h1, l1;
                split2(acc[mt][nt][0], acc[mt][nt][1], h0, l0);
                split2(acc[mt][nt][2], acc[mt][nt][3], h1, l1);
                *(uint32_t*)(Ch + (size_t)row * N + col)       = h0;
                *(uint32_t*)(Cl + (size_t)row * N + col)       = l0;
                *(uint32_t*)(Ch + (size_t)(row + 8) * N + col) = h1;
                *(uint32_t*)(Cl + (size_t)(row + 8) * N + col) = l1;
            }
        }
    }
}

// ---------------------------------------------------------------------------
// Tensor-core flash attention (split-bf16, FA2 register dataflow). Unchanged.
// ---------------------------------------------------------------------------
#define AT_STRIDE 144
#define QARR  (128 * AT_STRIDE)
#define KVARR (64 * AT_STRIDE)
#define KV_STAGE (4 * KVARR)
#define AT_SMEM (2 * QARR + 2 * KV_STAGE)

__global__ void __launch_bounds__(256, 1)
flash_attn_tc(const __nv_bfloat16* __restrict__ qh_g,
              const __nv_bfloat16* __restrict__ ql_g,
              __nv_bfloat16* __restrict__ oh_g,
              __nv_bfloat16* __restrict__ ol_g)
{
    extern __shared__ __align__(16) char dsm[];
    const uint32_t sb  = smem_u32_of(dsm);
    const uint32_t sQh = sb, sQl = sb + QARR;
    const uint32_t sKV = sb + 2 * QARR;

    const int tid  = threadIdx.x;
    const int lane = tid & 31;
    const int wid  = tid >> 5;
    const int b    = blockIdx.y >> 4;
    const int h    = blockIdx.y & 15;
    const int n0   = blockIdx.x * 128;
    const int m0   = wid * 16;
    const int lr   = lane >> 2;
    const int lc   = lane & 3;

    const size_t rowbase = (size_t)b * NSEQ;
    const int    hoff    = h * DH;

    const uint32_t qa_off = (uint32_t)((m0 + (lane & 15)) * AT_STRIDE + ((lane >> 4) << 4));
    const int      k_rl   = (lane & 7) + ((lane & 16) >> 1);
    const uint32_t k_ch   = (uint32_t)(((lane >> 3) & 1) << 4);
    const int      v_rl   = (lane & 7) + (((lane >> 3) & 1) << 3);
    const uint32_t v_ch   = (uint32_t)(((lane >> 4) & 1) << 4);

#pragma unroll
    for (int i = 0; i < 8; i++) {
        int q = tid + i * 256;
        int arr = q >> 10;
        int r = (q & 1023) >> 3;
        int c = q & 7;
        const __nv_bfloat16* src = (arr ? ql_g : qh_g)
            + (rowbase + n0 + r) * QKVN + hoff + c * 8;
        cp16((arr ? sQl : sQh) + (uint32_t)(r * AT_STRIDE + c * 16), src);
    }

    auto issueKV = [&](int kv0, int stage) {
#pragma unroll
        for (int i = 0; i < 8; i++) {
            int q = tid + i * 256;
            int arr = q >> 9;
            int r = (q & 511) >> 3;
            int c = q & 7;
            const __nv_bfloat16* base = (arr & 1) ? ql_g : qh_g;
            int coff = ((arr >> 1) ? 2 * DIMC : DIMC) + hoff + c * 8;
            const __nv_bfloat16* src = base + (rowbase + kv0 + r) * QKVN + coff;
            cp16(sKV + (uint32_t)(stage * KV_STAGE + arr * KVARR + r * AT_STRIDE + c * 16), src);
        }
    };

    issueKV(0, 0);
    CP_COMMIT();

    const float NEG_INF = __int_as_float(0xff800000);
    float m0s = NEG_INF, m1s = NEG_INF, l0s = 0.f, l1s = 0.f;
    float o[8][4];
#pragma unroll
    for (int nt = 0; nt < 8; nt++)
#pragma unroll
        for (int j = 0; j < 4; j++) o[nt][j] = 0.f;

    int stage = 0;
    for (int it = 0; it < NSEQ / 64; it++) {
        if (it + 1 < NSEQ / 64) {
            issueKV((it + 1) * 64, stage ^ 1);
            CP_COMMIT();
            CP_WAIT(1);
        } else {
            CP_WAIT(0);
        }
        __syncthreads();

        const uint32_t sK  = sKV + (uint32_t)(stage * KV_STAGE);
        const uint32_t sKh = sK, sKl = sK + KVARR;
        const uint32_t sVh = sK + 2 * KVARR, sVl = sK + 3 * KVARR;

        float c[8][4];
#pragma unroll
        for (int nt = 0; nt < 8; nt++)
#pragma unroll
            for (int j = 0; j < 4; j++) c[nt][j] = 0.f;

#pragma unroll
        for (int kt = 0; kt < 4; kt++) {
            uint32_t qh4[4], ql4[4];
            ldsm4(qh4, sQh + qa_off + 32 * kt);
            ldsm4(ql4, sQl + qa_off + 32 * kt);
#pragma unroll
            for (int p = 0; p < 4; p++) {
                uint32_t kh4[4], kl4[4];
                uint32_t ko = (uint32_t)((p * 16 + k_rl) * AT_STRIDE) + k_ch + 32 * kt;
                ldsm4(kh4, sKh + ko);
                ldsm4(kl4, sKl + ko);
                mma_b(c[2 * p],     qh4, kh4[0], kh4[1]);
                mma_b(c[2 * p],     qh4, kl4[0], kl4[1]);
                mma_b(c[2 * p],     ql4, kh4[0], kh4[1]);
                mma_b(c[2 * p + 1], qh4, kh4[2], kh4[3]);
                mma_b(c[2 * p + 1], qh4, kl4[2], kl4[3]);
                mma_b(c[2 * p + 1], ql4, kh4[2], kh4[3]);
            }
        }

        float mt0 = NEG_INF, mt1 = NEG_INF;
#pragma unroll
        for (int nt = 0; nt < 8; nt++) {
            c[nt][0] *= SCALE; c[nt][1] *= SCALE;
            c[nt][2] *= SCALE; c[nt][3] *= SCALE;
            mt0 = fmaxf(mt0, fmaxf(c[nt][0], c[nt][1]));
            mt1 = fmaxf(mt1, fmaxf(c[nt][2], c[nt][3]));
        }
        mt0 = fmaxf(mt0, __shfl_xor_sync(0xffffffffu, mt0, 1));
        mt0 = fmaxf(mt0, __shfl_xor_sync(0xffffffffu, mt0, 2));
        mt1 = fmaxf(mt1, __shfl_xor_sync(0xffffffffu, mt1, 1));
        mt1 = fmaxf(mt1, __shfl_xor_sync(0xffffffffu, mt1, 2));

        float mn0 = fmaxf(m0s, mt0), mn1 = fmaxf(m1s, mt1);
        float corr0 = __expf(m0s - mn0), corr1 = __expf(m1s - mn1);
        m0s = mn0; m1s = mn1;

        float rs0 = 0.f, rs1 = 0.f;
#pragma unroll
        for (int nt = 0; nt < 8; nt++) {
            c[nt][0] = __expf(c[nt][0] - mn0);
            c[nt][1] = __expf(c[nt][1] - mn0);
            c[nt][2] = __expf(c[nt][2] - mn1);
            c[nt][3] = __expf(c[nt][3] - mn1);
            rs0 += c[nt][0] + c[nt][1];
            rs1 += c[nt][2] + c[nt][3];
        }
        rs0 += __shfl_xor_sync(0xffffffffu, rs0, 1);
        rs0 += __shfl_xor_sync(0xffffffffu, rs0, 2);
        rs1 += __shfl_xor_sync(0xffffffffu, rs1, 1);
        rs1 += __shfl_xor_sync(0xffffffffu, rs1, 2);
        l0s = l0s * corr0 + rs0;
        l1s = l1s * corr1 + rs1;

        uint32_t aph[4][4], apl[4][4];
#pragma unroll
        for (int kt = 0; kt < 4; kt++) {
            split2(c[2 * kt][0],     c[2 * kt][1],     aph[kt][0], apl[kt][0]);
            split2(c[2 * kt][2],     c[2 * kt][3],     aph[kt][1], apl[kt][1]);
            split2(c[2 * kt + 1][0], c[2 * kt + 1][1], aph[kt][2], apl[kt][2]);
            split2(c[2 * kt + 1][2], c[2 * kt + 1][3], aph[kt][3], apl[kt][3]);
        }

#pragma unroll
        for (int nt = 0; nt < 8; nt++) {
            o[nt][0] *= corr0; o[nt][1] *= corr0;
            o[nt][2] *= corr1; o[nt][3] *= corr1;
        }

#pragma unroll
        for (int kt = 0; kt < 4; kt++) {
#pragma unroll
            for (int g = 0; g < 4; g++) {
                uint32_t vh4[4], vl4[4];
                uint32_t vo = (uint32_t)((16 * kt + v_rl) * AT_STRIDE) + 32 * g + v_ch;
                ldsm4t(vh4, sVh + vo);
                ldsm4t(vl4, sVl + vo);
                mma_b(o[2 * g],     aph[kt], vh4[0], vh4[1]);
                mma_b(o[2 * g],     aph[kt], vl4[0], vl4[1]);
                mma_b(o[2 * g],     apl[kt], vh4[0], vh4[1]);
                mma_b(o[2 * g + 1], aph[kt], vh4[2], vh4[3]);
                mma_b(o[2 * g + 1], aph[kt], vl4[2], vl4[3]);
                mma_b(o[2 * g + 1], apl[kt], vh4[2], vh4[3]);
            }
        }
        __syncthreads();
        stage ^= 1;
    }

    const float inv0 = 1.f / l0s, inv1 = 1.f / l1s;
    const size_t r0 = rowbase + n0 + m0 + lr;
    const size_t r1 = r0 + 8;
#pragma unroll
    for (int nt = 0; nt < 8; nt++) {
        const int col = hoff + nt * 8 + 2 * lc;
        uint32_t h0, l0, h1, l1;
        split2(o[nt][0] * inv0, o[nt][1] * inv0, h0, l0);
        split2(o[nt][2] * inv1, o[nt][3] * inv1, h1, l1);
        *(uint32_t*)(oh_g + r0 * DIMC + col) = h0;
        *(uint32_t*)(ol_g + r0 * DIMC + col) = l0;
        *(uint32_t*)(oh_g + r1 * DIMC + col) = h1;
        *(uint32_t*)(ol_g + r1 * DIMC + col) = l1;
    }
}

// ---------------------------------------------------------------------------
extern "C" void kernel_launch(void* const* d_in, const int* in_sizes, int n_in,
                              void* d_out, int out_size)
{
    (void)in_sizes; (void)n_in; (void)out_size;
    const float* x      = (const float*)d_in[0];
    const float* w_qkv  = (const float*)d_in[1];
    const float* w_proj = (const float*)d_in[2];
    float* out = (float*)d_out;

    __nv_bfloat16 *qh, *ql, *xh, *xl, *wqh, *wql, *wph, *wpl, *ah, *al;
    cudaGetSymbolAddress((void**)&qh, g_qkvh); cudaGetSymbolAddress((void**)&ql, g_qkvl);
    cudaGetSymbolAddress((void**)&xh, g_xh);   cudaGetSymbolAddress((void**)&xl, g_xl);
    cudaGetSymbolAddress((void**)&wqh, g_wqh); cudaGetSymbolAddress((void**)&wql, g_wql);
    cudaGetSymbolAddress((void**)&wph, g_wph); cudaGetSymbolAddress((void**)&wpl, g_wpl);
    cudaGetSymbolAddress((void**)&ah, g_ah);   cudaGetSymbolAddress((void**)&al, g_al);

    static int cfg_done = 0;
    if (!cfg_done) {
        cudaFuncSetAttribute(gemm_hmma, cudaFuncAttributeMaxDynamicSharedMemorySize, GSMEM);
        cudaFuncSetAttribute(flash_attn_tc, cudaFuncAttributeMaxDynamicSharedMemorySize, AT_SMEM);
        cfg_done = 1;
    }

    // 0) split inputs to bf16 hi/lo
    {
        int n4 = MT * DIMC / 4;
        split_bf16<<<(n4 + 255) / 256, 256>>>((const float4*)x, xh, xl, n4);
        n4 = QKVN * DIMC / 4;
        split_bf16<<<(n4 + 255) / 256, 256>>>((const float4*)w_qkv, wqh, wql, n4);
        n4 = DIMC * DIMC / 4;
        split_bf16<<<(n4 + 255) / 256, 256>>>((const float4*)w_proj, wph, wpl, n4);
    }

    // 1) QKV projection -> split hi/lo bf16 qkv
    gemm_hmma<<<dim3(QKVN / 128, MT / 128), 256, GSMEM>>>(
        xh, xl, wqh, wql, nullptr, qh, ql, MT, QKVN, DIMC);

    // 2) Tensor-core flash attention
    flash_attn_tc<<<dim3(NSEQ / 128, NB * NH), 256, AT_SMEM>>>(qh, ql, ah, al);

    // 3) Output projection -> fp32 out
    gemm_hmma<<<dim3(DIMC / 128, MT / 128), 256, GSMEM>>>(
        ah, al, wph, wpl, out, nullptr, nullptr, MT, DIMC, DIMC);
}

// round 6
// speedup vs baseline: 6.6378x; 2.6184x over previous
#include <cuda_runtime.h>
#include <cuda_fp16.h>
#include <cstdint>

#define DIMC 1024
#define NB   4
#define NSEQ 2048
#define NH   16
#define DH   64
#define MT   (NB * NSEQ)      // 8192 rows
#define QKVN (3 * DIMC)       // 3072
#define SCALE 0.125f          // 64^-0.5

// ---------------- scratch (static device globals: allocation-free) ----------
__device__ __half g_x16[(size_t)MT * DIMC];
__device__ __half g_wq16[(size_t)QKVN * DIMC];
__device__ __half g_wp16[(size_t)DIMC * DIMC];
__device__ __half g_qkv16[(size_t)MT * QKVN];
__device__ __half g_a16[(size_t)MT * DIMC];

// ---------------- PTX helpers ------------------------------------------------
__device__ __forceinline__ uint32_t smem_u32_of(const void* p) {
    uint32_t a;
    asm("{ .reg .u64 t; cvta.to.shared.u64 t, %1; cvt.u32.u64 %0, t; }"
        : "=r"(a) : "l"(p));
    return a;
}
__device__ __forceinline__ void cp16(uint32_t dst, const void* src) {
    asm volatile("cp.async.cg.shared.global [%0], [%1], 16;" :: "r"(dst), "l"(src));
}
#define CP_COMMIT() asm volatile("cp.async.commit_group;" ::: "memory")
#define CP_WAIT(n)  asm volatile("cp.async.wait_group %0;" :: "n"(n) : "memory")

__device__ __forceinline__ void ldsm4(uint32_t* r, uint32_t a) {
    asm volatile("ldmatrix.sync.aligned.m8n8.x4.shared.b16 {%0,%1,%2,%3}, [%4];"
                 : "=r"(r[0]), "=r"(r[1]), "=r"(r[2]), "=r"(r[3]) : "r"(a));
}
__device__ __forceinline__ void ldsm4t(uint32_t* r, uint32_t a) {
    asm volatile("ldmatrix.sync.aligned.m8n8.x4.trans.shared.b16 {%0,%1,%2,%3}, [%4];"
                 : "=r"(r[0]), "=r"(r[1]), "=r"(r[2]), "=r"(r[3]) : "r"(a));
}
__device__ __forceinline__ void mma_h(float* d, const uint32_t* a, uint32_t b0, uint32_t b1) {
    asm volatile(
        "mma.sync.aligned.m16n8k16.row.col.f32.f16.f16.f32 "
        "{%0,%1,%2,%3}, {%4,%5,%6,%7}, {%8,%9}, {%0,%1,%2,%3};"
        : "+f"(d[0]), "+f"(d[1]), "+f"(d[2]), "+f"(d[3])
        : "r"(a[0]), "r"(a[1]), "r"(a[2]), "r"(a[3]), "r"(b0), "r"(b1));
}
__device__ __forceinline__ uint32_t pack_h2(float x, float y) {
    __half2 t = __floats2half2_rn(x, y);
    return *(uint32_t*)&t;
}

// ---------------------------------------------------------------------------
// convert fp32 -> fp16
// ---------------------------------------------------------------------------
__global__ void __launch_bounds__(256)
to_fp16(const float4* __restrict__ src, __half* __restrict__ dst, int n4)
{
    int i = blockIdx.x * blockDim.x + threadIdx.x;
    if (i >= n4) return;
    float4 v = src[i];
    uint32_t p0 = pack_h2(v.x, v.y);
    uint32_t p1 = pack_h2(v.z, v.w);
    size_t o = (size_t)i * 4;
    *(uint32_t*)(dst + o)     = p0;
    *(uint32_t*)(dst + o + 2) = p1;
}

// ---------------------------------------------------------------------------
// fp16 HMMA GEMM NT: C[M,N] = A[M,K] * B[N,K]^T, fp32 accum.
// 128x128 CTA tile, BK=32, 8 warps (2x4), warp tile 64x32.
// ldmatrix.x4; 3-stage cp.async, depth-2 prefetch, 2 CTAs/SM.
// Output: fp32 C (Ch==null) or fp16 Ch.
// ---------------------------------------------------------------------------
#define STRIDE_B 80
#define ARR_SZ   (128 * STRIDE_B)        // 10240
#define STAGE_SZ (2 * ARR_SZ)            // 20480 (A + B)
#define GSMEM    (3 * STAGE_SZ)          // 61440

__global__ void __launch_bounds__(256, 2)
gemm_hmma(const __half* __restrict__ A, const __half* __restrict__ B,
          float* __restrict__ C, __half* __restrict__ Ch, int M, int N, int K)
{
    extern __shared__ __align__(16) char dsm[];
    const uint32_t sb = smem_u32_of(dsm);

    const int tid  = threadIdx.x;
    const int wid  = tid >> 5;
    const int lane = tid & 31;
    const int wm   = wid & 1;
    const int wn   = wid >> 1;
    const int bm   = blockIdx.y * 128;
    const int bn   = blockIdx.x * 128;
    const int lr   = lane >> 2;
    const int lc2  = (lane & 3) * 2;

    // cp.async mapping: 512 16B-chunks per array per stage; 2 per thread
    const int r0 = (tid * 2) >> 2, c0 = (tid * 2) & 3;
    const int r1 = (tid * 2 + 1) >> 2, c1 = (tid * 2 + 1) & 3;

    // ldmatrix lane patterns
    const uint32_t a_off = (uint32_t)((wm * 64 + (lane & 15)) * STRIDE_B + ((lane >> 4) << 4));
    const int      k_rl  = (lane & 7) + ((lane & 16) >> 1);
    const uint32_t k_ch  = (uint32_t)(((lane >> 3) & 1) << 4);

    float acc[4][4][4];
#pragma unroll
    for (int i = 0; i < 4; i++)
#pragma unroll
        for (int j = 0; j < 4; j++)
#pragma unroll
            for (int k = 0; k < 4; k++) acc[i][j][k] = 0.f;

    const int nk = K >> 5;

    auto issue = [&](int chunk, int stage) {
        const int k0 = chunk << 5;
        const uint32_t s = sb + stage * STAGE_SZ;
        const uint32_t so0 = (uint32_t)(r0 * STRIDE_B + c0 * 16);
        const uint32_t so1 = (uint32_t)(r1 * STRIDE_B + c1 * 16);
        cp16(s + so0,          A + (size_t)(bm + r0) * K + k0 + c0 * 8);
        cp16(s + so1,          A + (size_t)(bm + r1) * K + k0 + c1 * 8);
        cp16(s + ARR_SZ + so0, B + (size_t)(bn + r0) * K + k0 + c0 * 8);
        cp16(s + ARR_SZ + so1, B + (size_t)(bn + r1) * K + k0 + c1 * 8);
    };

    issue(0, 0);
    CP_COMMIT();
    if (nk > 1) { issue(1, 1); CP_COMMIT(); }

    int stage = 0;
    for (int ch = 0; ch < nk; ch++) {
        if (ch + 1 < nk) { CP_WAIT(1); } else { CP_WAIT(0); }
        __syncthreads();
        if (ch + 2 < nk) {
            int ws = stage + 2; if (ws >= 3) ws -= 3;
            issue(ch + 2, ws);
            CP_COMMIT();
        }

        const uint32_t sA = sb + stage * STAGE_SZ;
        const uint32_t sB = sA + ARR_SZ;

#pragma unroll
        for (int ks = 0; ks < 2; ks++) {
            const uint32_t kb = (uint32_t)(ks * 32);
            uint32_t ah[4][4], bh[2][4];
#pragma unroll
            for (int mt = 0; mt < 4; mt++)
                ldsm4(ah[mt], sA + a_off + (uint32_t)(mt * 16 * STRIDE_B) + kb);
#pragma unroll
            for (int nt2 = 0; nt2 < 2; nt2++)
                ldsm4(bh[nt2], sB + (uint32_t)((wn * 32 + nt2 * 16 + k_rl) * STRIDE_B) + k_ch + kb);
#pragma unroll
            for (int mt = 0; mt < 4; mt++)
#pragma unroll
                for (int nt2 = 0; nt2 < 2; nt2++) {
                    mma_h(acc[mt][nt2 * 2],     ah[mt], bh[nt2][0], bh[nt2][1]);
                    mma_h(acc[mt][nt2 * 2 + 1], ah[mt], bh[nt2][2], bh[nt2][3]);
                }
        }
        stage++; if (stage >= 3) stage = 0;
    }

    if (Ch == nullptr) {
#pragma unroll
        for (int mt = 0; mt < 4; mt++) {
            const int row = bm + wm * 64 + mt * 16 + lr;
#pragma unroll
            for (int nt = 0; nt < 4; nt++) {
                const int col = bn + wn * 32 + nt * 8 + lc2;
                *(float2*)(C + (size_t)row * N + col) =
                    make_float2(acc[mt][nt][0], acc[mt][nt][1]);
                *(float2*)(C + (size_t)(row + 8) * N + col) =
                    make_float2(acc[mt][nt][2], acc[mt][nt][3]);
            }
        }
    } else {
#pragma unroll
        for (int mt = 0; mt < 4; mt++) {
            const int row = bm + wm * 64 + mt * 16 + lr;
#pragma unroll
            for (int nt = 0; nt < 4; nt++) {
                const int col = bn + wn * 32 + nt * 8 + lc2;
                *(uint32_t*)(Ch + (size_t)row * N + col) =
                    pack_h2(acc[mt][nt][0], acc[mt][nt][1]);
                *(uint32_t*)(Ch + (size_t)(row + 8) * N + col) =
                    pack_h2(acc[mt][nt][2], acc[mt][nt][3]);
            }
        }
    }
}

// ---------------------------------------------------------------------------
// Tensor-core flash attention, fp16 single-product, FA2 register dataflow.
// CTA: 128 q-rows x one (b,h). 8 warps; KV tiles of 64, double-buffered.
// ---------------------------------------------------------------------------
#define AT_STRIDE 144
#define QARR  (128 * AT_STRIDE)            // 18432
#define KVARR (64 * AT_STRIDE)             // 9216
#define KV_STAGE (2 * KVARR)               // 18432 (K + V)
#define AT_SMEM (QARR + 2 * KV_STAGE)      // 55296

__global__ void __launch_bounds__(256, 2)
flash_attn_tc(const __half* __restrict__ qkv, __half* __restrict__ o_g)
{
    extern __shared__ __align__(16) char dsm[];
    const uint32_t sb  = smem_u32_of(dsm);
    const uint32_t sQ  = sb;
    const uint32_t sKV = sb + QARR;

    const int tid  = threadIdx.x;
    const int lane = tid & 31;
    const int wid  = tid >> 5;
    const int b    = blockIdx.y >> 4;
    const int h    = blockIdx.y & 15;
    const int n0   = blockIdx.x * 128;
    const int m0   = wid * 16;
    const int lr   = lane >> 2;
    const int lc   = lane & 3;

    const size_t rowbase = (size_t)b * NSEQ;
    const int    hoff    = h * DH;

    const uint32_t qa_off = (uint32_t)((m0 + (lane & 15)) * AT_STRIDE + ((lane >> 4) << 4));
    const int      k_rl   = (lane & 7) + ((lane & 16) >> 1);
    const uint32_t k_ch   = (uint32_t)(((lane >> 3) & 1) << 4);
    const int      v_rl   = (lane & 7) + (((lane >> 3) & 1) << 3);
    const uint32_t v_ch   = (uint32_t)(((lane >> 4) & 1) << 4);

    // ---- issue Q tile (once): 1024 16B chunks ----
#pragma unroll
    for (int i = 0; i < 4; i++) {
        int q = tid + i * 256;
        int r = q >> 3;
        int c = q & 7;
        cp16(sQ + (uint32_t)(r * AT_STRIDE + c * 16),
             qkv + (rowbase + n0 + r) * QKVN + hoff + c * 8);
    }

    auto issueKV = [&](int kv0, int stage) {
#pragma unroll
        for (int i = 0; i < 4; i++) {
            int q = tid + i * 256;
            int arr = q >> 9;               // 0=K 1=V
            int r = (q & 511) >> 3;
            int c = q & 7;
            int coff = (arr ? 2 * DIMC : DIMC) + hoff + c * 8;
            cp16(sKV + (uint32_t)(stage * KV_STAGE + arr * KVARR + r * AT_STRIDE + c * 16),
                 qkv + (rowbase + kv0 + r) * QKVN + coff);
        }
    };

    issueKV(0, 0);
    CP_COMMIT();

    const float NEG_INF = __int_as_float(0xff800000);
    float m0s = NEG_INF, m1s = NEG_INF, l0s = 0.f, l1s = 0.f;
    float o[8][4];
#pragma unroll
    for (int nt = 0; nt < 8; nt++)
#pragma unroll
        for (int j = 0; j < 4; j++) o[nt][j] = 0.f;

    int stage = 0;
    for (int it = 0; it < NSEQ / 64; it++) {
        if (it + 1 < NSEQ / 64) {
            issueKV((it + 1) * 64, stage ^ 1);
            CP_COMMIT();
            CP_WAIT(1);
        } else {
            CP_WAIT(0);
        }
        __syncthreads();

        const uint32_t sK = sKV + (uint32_t)(stage * KV_STAGE);
        const uint32_t sV = sK + KVARR;

        // ---- S = Q K^T ----
        float c[8][4];
#pragma unroll
        for (int nt = 0; nt < 8; nt++)
#pragma unroll
            for (int j = 0; j < 4; j++) c[nt][j] = 0.f;

#pragma unroll
        for (int kt = 0; kt < 4; kt++) {
            uint32_t q4[4];
            ldsm4(q4, sQ + qa_off + 32 * kt);
#pragma unroll
            for (int p = 0; p < 4; p++) {
                uint32_t k4[4];
                ldsm4(k4, sK + (uint32_t)((p * 16 + k_rl) * AT_STRIDE) + k_ch + 32 * kt);
                mma_h(c[2 * p],     q4, k4[0], k4[1]);
                mma_h(c[2 * p + 1], q4, k4[2], k4[3]);
            }
        }

        // ---- online softmax ----
        float mt0 = NEG_INF, mt1 = NEG_INF;
#pragma unroll
        for (int nt = 0; nt < 8; nt++) {
            c[nt][0] *= SCALE; c[nt][1] *= SCALE;
            c[nt][2] *= SCALE; c[nt][3] *= SCALE;
            mt0 = fmaxf(mt0, fmaxf(c[nt][0], c[nt][1]));
            mt1 = fmaxf(mt1, fmaxf(c[nt][2], c[nt][3]));
        }
        mt0 = fmaxf(mt0, __shfl_xor_sync(0xffffffffu, mt0, 1));
        mt0 = fmaxf(mt0, __shfl_xor_sync(0xffffffffu, mt0, 2));
        mt1 = fmaxf(mt1, __shfl_xor_sync(0xffffffffu, mt1, 1));
        mt1 = fmaxf(mt1, __shfl_xor_sync(0xffffffffu, mt1, 2));

        float mn0 = fmaxf(m0s, mt0), mn1 = fmaxf(m1s, mt1);
        float corr0 = __expf(m0s - mn0), corr1 = __expf(m1s - mn1);
        m0s = mn0; m1s = mn1;

        float rs0 = 0.f, rs1 = 0.f;
#pragma unroll
        for (int nt = 0; nt < 8; nt++) {
            c[nt][0] = __expf(c[nt][0] - mn0);
            c[nt][1] = __expf(c[nt][1] - mn0);
            c[nt][2] = __expf(c[nt][2] - mn1);
            c[nt][3] = __expf(c[nt][3] - mn1);
            rs0 += c[nt][0] + c[nt][1];
            rs1 += c[nt][2] + c[nt][3];
        }
        rs0 += __shfl_xor_sync(0xffffffffu, rs0, 1);
        rs0 += __shfl_xor_sync(0xffffffffu, rs0, 2);
        rs1 += __shfl_xor_sync(0xffffffffu, rs1, 1);
        rs1 += __shfl_xor_sync(0xffffffffu, rs1, 2);
        l0s = l0s * corr0 + rs0;
        l1s = l1s * corr1 + rs1;

        // ---- pack P fragments (A operand of PV) ----
        uint32_t ap[4][4];
#pragma unroll
        for (int kt = 0; kt < 4; kt++) {
            ap[kt][0] = pack_h2(c[2 * kt][0],     c[2 * kt][1]);
            ap[kt][1] = pack_h2(c[2 * kt][2],     c[2 * kt][3]);
            ap[kt][2] = pack_h2(c[2 * kt + 1][0], c[2 * kt + 1][1]);
            ap[kt][3] = pack_h2(c[2 * kt + 1][2], c[2 * kt + 1][3]);
        }

        // ---- rescale O ----
#pragma unroll
        for (int nt = 0; nt < 8; nt++) {
            o[nt][0] *= corr0; o[nt][1] *= corr0;
            o[nt][2] *= corr1; o[nt][3] *= corr1;
        }

        // ---- O += P V ----
#pragma unroll
        for (int kt = 0; kt < 4; kt++) {
#pragma unroll
            for (int g = 0; g < 4; g++) {
                uint32_t v4[4];
                ldsm4t(v4, sV + (uint32_t)((16 * kt + v_rl) * AT_STRIDE) + 32 * g + v_ch);
                mma_h(o[2 * g],     ap[kt], v4[0], v4[1]);
                mma_h(o[2 * g + 1], ap[kt], v4[2], v4[3]);
            }
        }
        __syncthreads();
        stage ^= 1;
    }

    // ---- epilogue: normalize, fp16, store [b, n, h, d] ----
    const float inv0 = 1.f / l0s, inv1 = 1.f / l1s;
    const size_t r0 = rowbase + n0 + m0 + lr;
    const size_t r1 = r0 + 8;
#pragma unroll
    for (int nt = 0; nt < 8; nt++) {
        const int col = hoff + nt * 8 + 2 * lc;
        *(uint32_t*)(o_g + r0 * DIMC + col) = pack_h2(o[nt][0] * inv0, o[nt][1] * inv0);
        *(uint32_t*)(o_g + r1 * DIMC + col) = pack_h2(o[nt][2] * inv1, o[nt][3] * inv1);
    }
}

// ---------------------------------------------------------------------------
extern "C" void kernel_launch(void* const* d_in, const int* in_sizes, int n_in,
                              void* d_out, int out_size)
{
    (void)in_sizes; (void)n_in; (void)out_size;
    const float* x      = (const float*)d_in[0];
    const float* w_qkv  = (const float*)d_in[1];
    const float* w_proj = (const float*)d_in[2];
    float* out = (float*)d_out;

    __half *x16, *wq16, *wp16, *qkv16, *a16;
    cudaGetSymbolAddress((void**)&x16,  g_x16);
    cudaGetSymbolAddress((void**)&wq16, g_wq16);
    cudaGetSymbolAddress((void**)&wp16, g_wp16);
    cudaGetSymbolAddress((void**)&qkv16, g_qkv16);
    cudaGetSymbolAddress((void**)&a16,  g_a16);

    static int cfg_done = 0;
    if (!cfg_done) {
        cudaFuncSetAttribute(gemm_hmma, cudaFuncAttributeMaxDynamicSharedMemorySize, GSMEM);
        cudaFuncSetAttribute(flash_attn_tc, cudaFuncAttributeMaxDynamicSharedMemorySize, AT_SMEM);
        cfg_done = 1;
    }

    // 0) convert inputs to fp16
    {
        int n4 = MT * DIMC / 4;
        to_fp16<<<(n4 + 255) / 256, 256>>>((const float4*)x, x16, n4);
        n4 = QKVN * DIMC / 4;
        to_fp16<<<(n4 + 255) / 256, 256>>>((const float4*)w_qkv, wq16, n4);
        n4 = DIMC * DIMC / 4;
        to_fp16<<<(n4 + 255) / 256, 256>>>((const float4*)w_proj, wp16, n4);
    }

    // 1) QKV projection -> fp16 qkv
    gemm_hmma<<<dim3(QKVN / 128, MT / 128), 256, GSMEM>>>(
        x16, wq16, nullptr, qkv16, MT, QKVN, DIMC);

    // 2) Tensor-core flash attention -> fp16 attn out
    flash_attn_tc<<<dim3(NSEQ / 128, NB * NH), 256, AT_SMEM>>>(qkv16, a16);

    // 3) Output projection -> fp32 out
    gemm_hmma<<<dim3(DIMC / 128, MT / 128), 256, GSMEM>>>(
        a16, wp16, out, nullptr, MT, DIMC, DIMC);
}